// round 1
// baseline (speedup 1.0000x reference)
#include <cuda_runtime.h>
#include <math.h>

#define BATCH 4
#define SEQ   2048
#define EMB   2048
#define HEAD  128
#define NQT   (SEQ/64)

// Scratch (device globals — no runtime allocation allowed)
__device__ float g_Q[BATCH*SEQ*HEAD];
__device__ float g_K[BATCH*SEQ*HEAD];
__device__ float g_VT[SEQ*HEAD];   // g_VT[k][h] = W_V[h][k]

// ---------------------------------------------------------------------------
// Transpose W_V [128,2048] -> g_VT [2048,128]
// ---------------------------------------------------------------------------
__global__ void transpose_v_kernel(const float* __restrict__ WV)
{
    int id = blockIdx.x * 256 + threadIdx.x;   // 0 .. 2048*128-1
    int k = id >> 7;
    int h = id & 127;
    g_VT[id] = WV[h * EMB + k];
}

// ---------------------------------------------------------------------------
// Projection GEMM: C[8192 x 256] = X[8192 x 2048] @ concat(WQ;WK)^T
// BM=128, BN=128 (y=0 -> WQ, y=1 -> WK), BK=16, 256 threads, 8x8 microtile.
// ---------------------------------------------------------------------------
__global__ __launch_bounds__(256) void proj_kernel(
    const float* __restrict__ X,
    const float* __restrict__ WQ,
    const float* __restrict__ WK)
{
    __shared__ float As[16][132];   // X tile, transposed: As[k][m]
    __shared__ float Bs[16][132];   // W tile, transposed: Bs[k][n]

    const int m0 = blockIdx.x * 128;
    const float* __restrict__ W = (blockIdx.y == 0) ? WQ : WK;

    const int tid = threadIdx.x;
    const int tr = tid >> 4;    // 0..15
    const int tc = tid & 15;    // 0..15

    const int lrow = tid >> 1;         // 0..127
    const int lk8  = (tid & 1) * 8;    // 0 or 8

    float acc[8][8];
#pragma unroll
    for (int i = 0; i < 8; i++)
#pragma unroll
        for (int j = 0; j < 8; j++) acc[i][j] = 0.f;

    const float* xptr = X + (long)(m0 + lrow) * EMB + lk8;
    const float* wptr = W + (long)lrow * EMB + lk8;

    for (int k0 = 0; k0 < EMB; k0 += 16) {
        float4 x0 = *(const float4*)(xptr + k0);
        float4 x1 = *(const float4*)(xptr + k0 + 4);
        float4 w0 = *(const float4*)(wptr + k0);
        float4 w1 = *(const float4*)(wptr + k0 + 4);

        As[lk8+0][lrow] = x0.x; As[lk8+1][lrow] = x0.y;
        As[lk8+2][lrow] = x0.z; As[lk8+3][lrow] = x0.w;
        As[lk8+4][lrow] = x1.x; As[lk8+5][lrow] = x1.y;
        As[lk8+6][lrow] = x1.z; As[lk8+7][lrow] = x1.w;

        Bs[lk8+0][lrow] = w0.x; Bs[lk8+1][lrow] = w0.y;
        Bs[lk8+2][lrow] = w0.z; Bs[lk8+3][lrow] = w0.w;
        Bs[lk8+4][lrow] = w1.x; Bs[lk8+5][lrow] = w1.y;
        Bs[lk8+6][lrow] = w1.z; Bs[lk8+7][lrow] = w1.w;

        __syncthreads();

#pragma unroll
        for (int kk = 0; kk < 16; kk++) {
            float a[8], b[8];
            *(float4*)&a[0] = *(const float4*)&As[kk][tr*8];
            *(float4*)&a[4] = *(const float4*)&As[kk][tr*8 + 4];
            *(float4*)&b[0] = *(const float4*)&Bs[kk][tc*8];
            *(float4*)&b[4] = *(const float4*)&Bs[kk][tc*8 + 4];
#pragma unroll
            for (int i = 0; i < 8; i++)
#pragma unroll
                for (int j = 0; j < 8; j++)
                    acc[i][j] += a[i] * b[j];
        }
        __syncthreads();
    }

    float* __restrict__ dst = (blockIdx.y == 0) ? g_Q : g_K;
#pragma unroll
    for (int i = 0; i < 8; i++) {
        int m = m0 + tr*8 + i;
#pragma unroll
        for (int j = 0; j < 8; j += 4) {
            float4 v = make_float4(acc[i][j], acc[i][j+1], acc[i][j+2], acc[i][j+3]);
            *(float4*)&dst[(long)m * HEAD + tc*8 + j] = v;
        }
    }
}

// ---------------------------------------------------------------------------
// Causal flash attention with V = W_V^T (shared across batch).
// One block per (batch, 64-row q-tile). 256 threads.
// S-tile 64x64, outer-product 4x4 microtile; O tile 64x128, 4x8 / thread.
// ---------------------------------------------------------------------------
#define QS_STRIDE 68
#define PS_STRIDE 65
#define QS_OFF    0
#define KS_OFF    (128*QS_STRIDE)                 // 8704
#define VS_OFF    (KS_OFF + 128*QS_STRIDE)        // 17408
#define PS_OFF    (VS_OFF + 64*128)               // 25600
#define SMEM_FLOATS (PS_OFF + 64*PS_STRIDE)       // 29760
#define SMEM_BYTES  (SMEM_FLOATS * 4)             // 119040

__global__ __launch_bounds__(256) void flash_kernel(float* __restrict__ out)
{
    extern __shared__ float sm[];
    float* Qs = sm + QS_OFF;   // [128][68] : Qs[d][r]  (transposed, scaled)
    float* Ks = sm + KS_OFF;   // [128][68] : Ks[d][c]
    float* Vs = sm + VS_OFF;   // [64][128] : Vs[kk][h]
    float* Ps = sm + PS_OFF;   // [64][65]  : Ps[r][kk]

    const int tid = threadIdx.x;
    const int tr = tid >> 4;   // 0..15 (row group: rows tr*4..tr*4+3)
    const int tc = tid & 15;   // 0..15

    const int b  = blockIdx.x >> 5;   // NQT = 32
    const int qt = blockIdx.x & 31;

    const float scale = 0.08838834764831845f;   // 1/sqrt(128)

    // Load Q tile transposed + pre-scaled
    const float* __restrict__ Qg = g_Q + (long)(b * SEQ + qt * 64) * HEAD;
    for (int i = tid; i < 64 * 128; i += 256) {
        int r = i >> 7, d = i & 127;
        Qs[d * QS_STRIDE + r] = Qg[i] * scale;
    }

    float o[4][8];
#pragma unroll
    for (int i = 0; i < 4; i++)
#pragma unroll
        for (int j = 0; j < 8; j++) o[i][j] = 0.f;
    float m_i[4] = {-1e30f, -1e30f, -1e30f, -1e30f};
    float l_i[4] = {0.f, 0.f, 0.f, 0.f};

    for (int kt = 0; kt <= qt; kt++) {
        __syncthreads();   // protect Ks/Vs from prior readers; makes Qs visible (iter 0)

        const float* __restrict__ Kg = g_K + (long)(b * SEQ + kt * 64) * HEAD;
        for (int i = tid; i < 64 * 128; i += 256) {
            int r = i >> 7, d = i & 127;
            Ks[d * QS_STRIDE + r] = Kg[i];
        }
        const float* __restrict__ Vg = g_VT + (long)(kt * 64) * HEAD;
        for (int i = tid; i < 64 * 128; i += 256) {
            Vs[i] = Vg[i];
        }
        __syncthreads();

        // ---- S = Q K^T (scaled), 4x4 per thread via outer products ----
        float s[4][4];
#pragma unroll
        for (int i = 0; i < 4; i++)
#pragma unroll
            for (int j = 0; j < 4; j++) s[i][j] = 0.f;

#pragma unroll 8
        for (int d = 0; d < 128; d++) {
            float4 a = *(const float4*)&Qs[d * QS_STRIDE + tr * 4];
            float4 kv = *(const float4*)&Ks[d * QS_STRIDE + tc * 4];
            float av[4] = {a.x, a.y, a.z, a.w};
            float bv[4] = {kv.x, kv.y, kv.z, kv.w};
#pragma unroll
            for (int i = 0; i < 4; i++)
#pragma unroll
                for (int j = 0; j < 4; j++)
                    s[i][j] += av[i] * bv[j];
        }

        // ---- mask + online softmax bookkeeping ----
#pragma unroll
        for (int i = 0; i < 4; i++) {
            const int qrow = qt * 64 + tr * 4 + i;
            float sv[4];
            float rowmax = -1e30f;
#pragma unroll
            for (int j = 0; j < 4; j++) {
                int kcol = kt * 64 + tc * 4 + j;
                float v = (kcol <= qrow) ? s[i][j] : -1e30f;
                sv[j] = v;
                rowmax = fmaxf(rowmax, v);
            }
            // reduce max over the 16 lanes sharing this row group
#pragma unroll
            for (int off = 8; off >= 1; off >>= 1)
                rowmax = fmaxf(rowmax, __shfl_xor_sync(0xffffffffu, rowmax, off));

            float mnew = fmaxf(m_i[i], rowmax);
            float fac  = __expf(m_i[i] - mnew);
            float psum = 0.f;
#pragma unroll
            for (int j = 0; j < 4; j++) {
                float p = __expf(sv[j] - mnew);
                Ps[(tr * 4 + i) * PS_STRIDE + tc * 4 + j] = p;
                psum += p;
            }
#pragma unroll
            for (int off = 8; off >= 1; off >>= 1)
                psum += __shfl_xor_sync(0xffffffffu, psum, off);

            l_i[i] = l_i[i] * fac + psum;
            m_i[i] = mnew;
#pragma unroll
            for (int j = 0; j < 8; j++) o[i][j] *= fac;
        }
        __syncthreads();

        // ---- O += P @ V : each thread owns rows tr*4..+3, cols tc*8..+7 ----
#pragma unroll 4
        for (int kk = 0; kk < 64; kk++) {
            float4 v0 = *(const float4*)&Vs[kk * 128 + tc * 8];
            float4 v1 = *(const float4*)&Vs[kk * 128 + tc * 8 + 4];
#pragma unroll
            for (int i = 0; i < 4; i++) {
                float p = Ps[(tr * 4 + i) * PS_STRIDE + kk];
                o[i][0] += p * v0.x; o[i][1] += p * v0.y;
                o[i][2] += p * v0.z; o[i][3] += p * v0.w;
                o[i][4] += p * v1.x; o[i][5] += p * v1.y;
                o[i][6] += p * v1.z; o[i][7] += p * v1.w;
            }
        }
    }

    // ---- normalize + write out ----
    float* __restrict__ Og = out + (long)(b * SEQ + qt * 64) * HEAD;
#pragma unroll
    for (int i = 0; i < 4; i++) {
        float inv = 1.0f / l_i[i];
        int r = tr * 4 + i;
        float4 w0 = make_float4(o[i][0]*inv, o[i][1]*inv, o[i][2]*inv, o[i][3]*inv);
        float4 w1 = make_float4(o[i][4]*inv, o[i][5]*inv, o[i][6]*inv, o[i][7]*inv);
        *(float4*)&Og[(long)r * HEAD + tc * 8]     = w0;
        *(float4*)&Og[(long)r * HEAD + tc * 8 + 4] = w1;
    }
}

// ---------------------------------------------------------------------------
extern "C" void kernel_launch(void* const* d_in, const int* in_sizes, int n_in,
                              void* d_out, int out_size)
{
    const float* X  = (const float*)d_in[0];
    const float* WQ = (const float*)d_in[1];
    const float* WK = (const float*)d_in[2];
    const float* WV = (const float*)d_in[3];
    float* out = (float*)d_out;

    cudaFuncSetAttribute(flash_kernel,
                         cudaFuncAttributeMaxDynamicSharedMemorySize, SMEM_BYTES);

    transpose_v_kernel<<<(SEQ * HEAD) / 256, 256>>>(WV);
    proj_kernel<<<dim3(64, 2), 256>>>(X, WQ, WK);
    flash_kernel<<<BATCH * NQT, 256, SMEM_BYTES>>>(out);
}

// round 2
// speedup vs baseline: 1.0410x; 1.0410x over previous
#include <cuda_runtime.h>
#include <math.h>

#define BATCH 4
#define SEQ   2048
#define EMB   2048
#define HEAD  128
#define NQT   (SEQ/64)

typedef unsigned long long u64;

// Scratch (device globals — no runtime allocation allowed)
__device__ float g_Q[BATCH*SEQ*HEAD];
__device__ float g_K[BATCH*SEQ*HEAD];
__device__ float g_VT[SEQ*HEAD];              // g_VT[k][h] = W_V[h][k]
__device__ float g_O[2][BATCH*SEQ*HEAD];      // unnormalized partial O per split
__device__ float g_m[2][BATCH*SEQ];           // row max per split
__device__ float g_l[2][BATCH*SEQ];           // row sum per split

// ---------------- f32x2 helpers (FFMA2 path, PTX-only) ----------------
__device__ __forceinline__ u64 pack2(float lo, float hi) {
    u64 r; asm("mov.b64 %0, {%1, %2};" : "=l"(r) : "f"(lo), "f"(hi)); return r;
}
__device__ __forceinline__ void unpack2(u64 v, float& lo, float& hi) {
    asm("mov.b64 {%0, %1}, %2;" : "=f"(lo), "=f"(hi) : "l"(v));
}
__device__ __forceinline__ u64 ffma2(u64 a, u64 b, u64 c) {
    u64 d; asm("fma.rn.f32x2 %0, %1, %2, %3;" : "=l"(d) : "l"(a), "l"(b), "l"(c)); return d;
}
__device__ __forceinline__ u64 fmul2(u64 a, u64 b) {
    u64 d; asm("mul.rn.f32x2 %0, %1, %2;" : "=l"(d) : "l"(a), "l"(b)); return d;
}

// ---------------------------------------------------------------------------
// Transpose W_V [128,2048] -> g_VT [2048,128]
// ---------------------------------------------------------------------------
__global__ void transpose_v_kernel(const float* __restrict__ WV)
{
    int id = blockIdx.x * 256 + threadIdx.x;
    int k = id >> 7;
    int h = id & 127;
    g_VT[id] = WV[h * EMB + k];
}

// ---------------------------------------------------------------------------
// Projection GEMM with f32x2 (k-pair packed): C[8192 x 256] = X @ [WQ;WK]^T
// BM=128, BN=128 (blockIdx.y selects WQ/WK), BK=16 (8 k-pairs), 256 thr, 8x8.
// ---------------------------------------------------------------------------
__global__ __launch_bounds__(256) void proj_kernel(
    const float* __restrict__ X,
    const float* __restrict__ WQ,
    const float* __restrict__ WK)
{
    __shared__ u64 As2[8 * 132];   // As2[k2*132 + m] = (X[m][2k2], X[m][2k2+1])
    __shared__ u64 Bs2[8 * 132];

    const int m0 = blockIdx.x * 128;
    const float* __restrict__ W = (blockIdx.y == 0) ? WQ : WK;

    const int tid = threadIdx.x;
    const int tr = tid >> 4;    // 0..15
    const int tc = tid & 15;    // 0..15

    const int lrow = tid >> 1;         // 0..127
    const int lk8  = (tid & 1) * 8;    // 0 or 8
    const int lk2  = lk8 >> 1;         // 0 or 4

    u64 acc2[8][8];
#pragma unroll
    for (int i = 0; i < 8; i++)
#pragma unroll
        for (int j = 0; j < 8; j++) acc2[i][j] = 0ULL;

    const float* xptr = X + (long)(m0 + lrow) * EMB + lk8;
    const float* wptr = W + (long)lrow * EMB + lk8;

    for (int k0 = 0; k0 < EMB; k0 += 16) {
        float4 x0 = *(const float4*)(xptr + k0);
        float4 x1 = *(const float4*)(xptr + k0 + 4);
        float4 w0 = *(const float4*)(wptr + k0);
        float4 w1 = *(const float4*)(wptr + k0 + 4);

        As2[(lk2+0)*132 + lrow] = pack2(x0.x, x0.y);
        As2[(lk2+1)*132 + lrow] = pack2(x0.z, x0.w);
        As2[(lk2+2)*132 + lrow] = pack2(x1.x, x1.y);
        As2[(lk2+3)*132 + lrow] = pack2(x1.z, x1.w);

        Bs2[(lk2+0)*132 + lrow] = pack2(w0.x, w0.y);
        Bs2[(lk2+1)*132 + lrow] = pack2(w0.z, w0.w);
        Bs2[(lk2+2)*132 + lrow] = pack2(w1.x, w1.y);
        Bs2[(lk2+3)*132 + lrow] = pack2(w1.z, w1.w);

        __syncthreads();

#pragma unroll
        for (int k2 = 0; k2 < 8; k2++) {
            u64 a2[8], b2[8];
#pragma unroll
            for (int q = 0; q < 4; q++) {
                ulonglong2 va = *(const ulonglong2*)&As2[k2*132 + tr*8 + q*2];
                a2[q*2+0] = va.x; a2[q*2+1] = va.y;
                ulonglong2 vb = *(const ulonglong2*)&Bs2[k2*132 + tc*8 + q*2];
                b2[q*2+0] = vb.x; b2[q*2+1] = vb.y;
            }
#pragma unroll
            for (int i = 0; i < 8; i++)
#pragma unroll
                for (int j = 0; j < 8; j++)
                    acc2[i][j] = ffma2(a2[i], b2[j], acc2[i][j]);
        }
        __syncthreads();
    }

    float* __restrict__ dst = (blockIdx.y == 0) ? g_Q : g_K;
#pragma unroll
    for (int i = 0; i < 8; i++) {
        int m = m0 + tr*8 + i;
        float c[8];
#pragma unroll
        for (int j = 0; j < 8; j++) {
            float lo, hi; unpack2(acc2[i][j], lo, hi);
            c[j] = lo + hi;
        }
        *(float4*)&dst[(long)m * HEAD + tc*8]     = make_float4(c[0], c[1], c[2], c[3]);
        *(float4*)&dst[(long)m * HEAD + tc*8 + 4] = make_float4(c[4], c[5], c[6], c[7]);
    }
}

// ---------------------------------------------------------------------------
// Causal flash attention, split-K (2 splits per q-tile), f32x2 packed.
// One block per (batch, q-tile, split). 256 threads.
// S-tile 64x64 (d-pair packed), O 64x128 (kk-pair packed), unnorm. partials.
// ---------------------------------------------------------------------------
#define QP 66                            // pair-row stride for Qs2/Ks2 (u64)
#define VP 130                           // pair-row stride for Vs2 (u64)
#define PS 66                            // row stride for Ps (floats)
#define QS2_OFF 0
#define KS2_OFF (64*QP)                  // 4224 u64
#define VS2_OFF (KS2_OFF + 64*QP)        // 8448 u64
#define PS_OFF_F ((VS2_OFF + 32*VP) * 2) // floats: (8448+4160)*2 = 25216
#define SMEM_FLOATS (PS_OFF_F + 64*PS)   // 29440
#define SMEM_BYTES  (SMEM_FLOATS * 4)    // 117760

__global__ __launch_bounds__(256) void flash_kernel()
{
    extern __shared__ float sm[];
    u64*   Qs2 = (u64*)sm + QS2_OFF;     // [64][QP]: (Q[2d2][r]*s, Q[2d2+1][r]*s)
    u64*   Ks2 = (u64*)sm + KS2_OFF;     // [64][QP]
    u64*   Vs2 = (u64*)sm + VS2_OFF;     // [32][VP]: (V[2k][h], V[2k+1][h])
    float* Qsf = (float*)Qs2;
    float* Ksf = (float*)Ks2;
    float* Vsf = (float*)Vs2;
    float* Ps  = sm + PS_OFF_F;          // [64][PS]

    const int tid = threadIdx.x;
    const int tr = tid >> 4;   // 0..15 (rows tr*4 .. tr*4+3)
    const int tc = tid & 15;   // 0..15

    // heavy-work-first block order: j -> (qt desc, b, par)
    const int j   = blockIdx.x;
    const int qt  = 31 - (j >> 3);
    const int b   = (j >> 1) & 3;
    const int par = j & 1;

    const int nkt   = qt + 1;
    const int half  = (nkt + 1) >> 1;
    const int kt_lo = par ? half : 0;
    const int kt_hi = par ? nkt  : half;

    const float scale = 0.08838834764831845f;   // 1/sqrt(128)

    // Load Q tile: pair-interleaved, transposed, pre-scaled
    const float* __restrict__ Qg = g_Q + (long)(b * SEQ + qt * 64) * HEAD;
    for (int i = tid; i < 64 * 128; i += 256) {
        int r = i >> 7, d = i & 127;
        Qsf[(d >> 1) * (2*QP) + r * 2 + (d & 1)] = Qg[i] * scale;
    }

    u64 o2[4][8];
#pragma unroll
    for (int i = 0; i < 4; i++)
#pragma unroll
        for (int jj = 0; jj < 8; jj++) o2[i][jj] = 0ULL;
    float m_i[4] = {-1e30f, -1e30f, -1e30f, -1e30f};
    float l_i[4] = {0.f, 0.f, 0.f, 0.f};

    for (int kt = kt_lo; kt < kt_hi; kt++) {
        __syncthreads();

        const float* __restrict__ Kg = g_K + (long)(b * SEQ + kt * 64) * HEAD;
        for (int i = tid; i < 64 * 128; i += 256) {
            int r = i >> 7, d = i & 127;
            Ksf[(d >> 1) * (2*QP) + r * 2 + (d & 1)] = Kg[i];
        }
        const float* __restrict__ Vg = g_VT + (long)(kt * 64) * HEAD;
        for (int i = tid; i < 64 * 128; i += 256) {
            int kk = i >> 7, h = i & 127;
            Vsf[(kk >> 1) * (2*VP) + h * 2 + (kk & 1)] = Vg[i];
        }
        __syncthreads();

        // ---- S = Q K^T, d-pair packed: 4x4 f32x2 accumulators ----
        u64 s2[4][4];
#pragma unroll
        for (int i = 0; i < 4; i++)
#pragma unroll
            for (int jj = 0; jj < 4; jj++) s2[i][jj] = 0ULL;

#pragma unroll 8
        for (int d2 = 0; d2 < 64; d2++) {
            u64 a2[4], b2[4];
            ulonglong2 qa0 = *(const ulonglong2*)&Qs2[d2*QP + tr*4];
            ulonglong2 qa1 = *(const ulonglong2*)&Qs2[d2*QP + tr*4 + 2];
            a2[0]=qa0.x; a2[1]=qa0.y; a2[2]=qa1.x; a2[3]=qa1.y;
            ulonglong2 kb0 = *(const ulonglong2*)&Ks2[d2*QP + tc*4];
            ulonglong2 kb1 = *(const ulonglong2*)&Ks2[d2*QP + tc*4 + 2];
            b2[0]=kb0.x; b2[1]=kb0.y; b2[2]=kb1.x; b2[3]=kb1.y;
#pragma unroll
            for (int i = 0; i < 4; i++)
#pragma unroll
                for (int jj = 0; jj < 4; jj++)
                    s2[i][jj] = ffma2(a2[i], b2[jj], s2[i][jj]);
        }

        // ---- mask + online softmax ----
#pragma unroll
        for (int i = 0; i < 4; i++) {
            const int qrow = qt * 64 + tr * 4 + i;
            float sv[4];
            float rowmax = -1e30f;
#pragma unroll
            for (int jj = 0; jj < 4; jj++) {
                float lo, hi; unpack2(s2[i][jj], lo, hi);
                float v = lo + hi;
                int kcol = kt * 64 + tc * 4 + jj;
                v = (kcol <= qrow) ? v : -1e30f;
                sv[jj] = v;
                rowmax = fmaxf(rowmax, v);
            }
#pragma unroll
            for (int off = 8; off >= 1; off >>= 1)
                rowmax = fmaxf(rowmax, __shfl_xor_sync(0xffffffffu, rowmax, off));

            float mnew = fmaxf(m_i[i], rowmax);
            float fac  = __expf(m_i[i] - mnew);
            float psum = 0.f;
#pragma unroll
            for (int jj = 0; jj < 4; jj++) {
                float p = __expf(sv[jj] - mnew);
                Ps[(tr * 4 + i) * PS + tc * 4 + jj] = p;
                psum += p;
            }
#pragma unroll
            for (int off = 8; off >= 1; off >>= 1)
                psum += __shfl_xor_sync(0xffffffffu, psum, off);

            l_i[i] = l_i[i] * fac + psum;
            m_i[i] = mnew;
            u64 facp = pack2(fac, fac);
#pragma unroll
            for (int jj = 0; jj < 8; jj++) o2[i][jj] = fmul2(o2[i][jj], facp);
        }
        __syncthreads();

        // ---- O += P @ V, kk-pair packed ----
#pragma unroll 4
        for (int k2 = 0; k2 < 32; k2++) {
            u64 v2[8];
#pragma unroll
            for (int q = 0; q < 4; q++) {
                ulonglong2 vv = *(const ulonglong2*)&Vs2[k2*VP + tc*8 + q*2];
                v2[q*2+0] = vv.x; v2[q*2+1] = vv.y;
            }
#pragma unroll
            for (int i = 0; i < 4; i++) {
                u64 p2 = *(const u64*)&Ps[(tr * 4 + i) * PS + k2 * 2];
#pragma unroll
                for (int jj = 0; jj < 8; jj++)
                    o2[i][jj] = ffma2(p2, v2[jj], o2[i][jj]);
            }
        }
    }

    // ---- write unnormalized partial O + (m, l) ----
    float* __restrict__ Og = g_O[par] + (long)(b * SEQ + qt * 64) * HEAD;
#pragma unroll
    for (int i = 0; i < 4; i++) {
        int r = tr * 4 + i;
        float c[8];
#pragma unroll
        for (int jj = 0; jj < 8; jj++) {
            float lo, hi; unpack2(o2[i][jj], lo, hi);
            c[jj] = lo + hi;
        }
        *(float4*)&Og[(long)r * HEAD + tc * 8]     = make_float4(c[0], c[1], c[2], c[3]);
        *(float4*)&Og[(long)r * HEAD + tc * 8 + 4] = make_float4(c[4], c[5], c[6], c[7]);
        if (tc == 0) {
            int row = b * SEQ + qt * 64 + r;
            g_m[par][row] = m_i[i];
            g_l[par][row] = l_i[i];
        }
    }
}

// ---------------------------------------------------------------------------
// Combine the two splits: out = (w0*O0 + w1*O1) / (w0*l0 + w1*l1)
// ---------------------------------------------------------------------------
__global__ void combine_kernel(float* __restrict__ out)
{
    int id = blockIdx.x * 256 + threadIdx.x;     // 0 .. B*S*H-1
    int row = id >> 7;
    float m0 = g_m[0][row], m1 = g_m[1][row];
    float l0 = g_l[0][row], l1 = g_l[1][row];
    float m  = fmaxf(m0, m1);
    float w0 = __expf(m0 - m);
    float w1 = __expf(m1 - m);
    float denom = w0 * l0 + w1 * l1;
    out[id] = (w0 * g_O[0][id] + w1 * g_O[1][id]) / denom;
}

// ---------------------------------------------------------------------------
extern "C" void kernel_launch(void* const* d_in, const int* in_sizes, int n_in,
                              void* d_out, int out_size)
{
    const float* X  = (const float*)d_in[0];
    const float* WQ = (const float*)d_in[1];
    const float* WK = (const float*)d_in[2];
    const float* WV = (const float*)d_in[3];
    float* out = (float*)d_out;

    cudaFuncSetAttribute(flash_kernel,
                         cudaFuncAttributeMaxDynamicSharedMemorySize, SMEM_BYTES);

    transpose_v_kernel<<<(SEQ * HEAD) / 256, 256>>>(WV);
    proj_kernel<<<dim3(64, 2), 256>>>(X, WQ, WK);
    flash_kernel<<<BATCH * NQT * 2, 256, SMEM_BYTES>>>();
    combine_kernel<<<(BATCH * SEQ * HEAD) / 256, 256>>>(out);
}

// round 3
// speedup vs baseline: 1.1624x; 1.1166x over previous
#include <cuda_runtime.h>
#include <math.h>

#define BATCH 4
#define SEQ   2048
#define EMB   2048
#define HEAD  128
#define NQT   (SEQ/64)

typedef unsigned long long u64;

// Scratch (device globals — no runtime allocation allowed)
__device__ float g_Q[BATCH*SEQ*HEAD];
__device__ float g_K[BATCH*SEQ*HEAD];
__device__ u64   g_QT2[BATCH*64*SEQ];     // [b][d2][s] = (Q[s][2d2]*sc, Q[s][2d2+1]*sc)
__device__ u64   g_KT2[BATCH*64*SEQ];     // [b][d2][s] = (K[s][2d2],    K[s][2d2+1])
__device__ u64   g_VT2[(SEQ/2)*HEAD];     // [k2][h]    = (V[2k2][h],    V[2k2+1][h]), V=W_V^T
__device__ float g_O[2][BATCH*SEQ*HEAD];  // unnormalized partial O per split
__device__ float g_m[2][BATCH*SEQ];
__device__ float g_l[2][BATCH*SEQ];

// ---------------- f32x2 helpers ----------------
__device__ __forceinline__ u64 pack2(float lo, float hi) {
    u64 r; asm("mov.b64 %0, {%1, %2};" : "=l"(r) : "f"(lo), "f"(hi)); return r;
}
__device__ __forceinline__ void unpack2(u64 v, float& lo, float& hi) {
    asm("mov.b64 {%0, %1}, %2;" : "=f"(lo), "=f"(hi) : "l"(v));
}
__device__ __forceinline__ u64 ffma2(u64 a, u64 b, u64 c) {
    u64 d; asm("fma.rn.f32x2 %0, %1, %2, %3;" : "=l"(d) : "l"(a), "l"(b), "l"(c)); return d;
}
__device__ __forceinline__ u64 fmul2(u64 a, u64 b) {
    u64 d; asm("mul.rn.f32x2 %0, %1, %2;" : "=l"(d) : "l"(a), "l"(b)); return d;
}

// ---------------- cp.async helpers ----------------
__device__ __forceinline__ void cp16(void* smem_dst, const void* gsrc) {
    unsigned sd = (unsigned)__cvta_generic_to_shared(smem_dst);
    asm volatile("cp.async.cg.shared.global [%0], [%1], 16;\n" :: "r"(sd), "l"(gsrc));
}
#define CP_COMMIT() asm volatile("cp.async.commit_group;\n" ::: "memory")
#define CP_WAIT(N)  asm volatile("cp.async.wait_group %0;\n" :: "n"(N) : "memory")

// ---------------------------------------------------------------------------
// Repack V: WV[128,2048] -> g_VT2[k2][h] pair-interleaved. Grid: 32 blocks.
// ---------------------------------------------------------------------------
__global__ __launch_bounds__(256) void repack_v_kernel(const float* __restrict__ WV)
{
    __shared__ float t[128][66];
    const int tid = threadIdx.x;
    const int k0  = blockIdx.x * 64;

    for (int i = tid; i < 128 * 64; i += 256) {
        int h = i >> 6, kk = i & 63;
        t[h][kk] = WV[h * EMB + k0 + kk];
    }
    __syncthreads();
    for (int j = tid; j < 32 * 128; j += 256) {
        int k2l = j >> 7, h = j & 127;
        g_VT2[((k0 >> 1) + k2l) * HEAD + h] = pack2(t[h][2*k2l], t[h][2*k2l + 1]);
    }
}

// ---------------------------------------------------------------------------
// Repack Q/K: g_Q|g_K [b][s][h] -> g_QT2|g_KT2 [b][d2][s] pair-interleaved.
// Grid: (256, 2). Q is pre-scaled by 1/sqrt(HEAD).
// ---------------------------------------------------------------------------
__global__ __launch_bounds__(256) void repack_qk_kernel()
{
    __shared__ float t[32][130];
    const int tid = threadIdx.x;
    const int b   = blockIdx.x >> 6;
    const int s0  = (blockIdx.x & 63) * 32;
    const int isK = blockIdx.y;

    const float* __restrict__ src = isK ? g_K : g_Q;
    u64* __restrict__ dst = isK ? g_KT2 : g_QT2;
    const float scl = isK ? 1.0f : 0.08838834764831845f;

    for (int i = tid; i < 32 * 128; i += 256) {
        int ss = i >> 7, h = i & 127;
        t[ss][h] = src[((long)(b * SEQ) + s0 + ss) * HEAD + h] * scl;
    }
    __syncthreads();
    for (int j = tid; j < 64 * 32; j += 256) {
        int d2 = j >> 5, ss = j & 31;
        dst[((long)(b * 64) + d2) * SEQ + s0 + ss] = pack2(t[ss][2*d2], t[ss][2*d2 + 1]);
    }
}

// ---------------------------------------------------------------------------
// Projection GEMM with f32x2 (unchanged, known-correct): C = X @ [WQ;WK]^T
// ---------------------------------------------------------------------------
__global__ __launch_bounds__(256) void proj_kernel(
    const float* __restrict__ X,
    const float* __restrict__ WQ,
    const float* __restrict__ WK)
{
    __shared__ u64 As2[8 * 132];
    __shared__ u64 Bs2[8 * 132];

    const int m0 = blockIdx.x * 128;
    const float* __restrict__ W = (blockIdx.y == 0) ? WQ : WK;

    const int tid = threadIdx.x;
    const int tr = tid >> 4;
    const int tc = tid & 15;
    const int lrow = tid >> 1;
    const int lk8  = (tid & 1) * 8;
    const int lk2  = lk8 >> 1;

    u64 acc2[8][8];
#pragma unroll
    for (int i = 0; i < 8; i++)
#pragma unroll
        for (int j = 0; j < 8; j++) acc2[i][j] = 0ULL;

    const float* xptr = X + (long)(m0 + lrow) * EMB + lk8;
    const float* wptr = W + (long)lrow * EMB + lk8;

    for (int k0 = 0; k0 < EMB; k0 += 16) {
        float4 x0 = *(const float4*)(xptr + k0);
        float4 x1 = *(const float4*)(xptr + k0 + 4);
        float4 w0 = *(const float4*)(wptr + k0);
        float4 w1 = *(const float4*)(wptr + k0 + 4);

        As2[(lk2+0)*132 + lrow] = pack2(x0.x, x0.y);
        As2[(lk2+1)*132 + lrow] = pack2(x0.z, x0.w);
        As2[(lk2+2)*132 + lrow] = pack2(x1.x, x1.y);
        As2[(lk2+3)*132 + lrow] = pack2(x1.z, x1.w);

        Bs2[(lk2+0)*132 + lrow] = pack2(w0.x, w0.y);
        Bs2[(lk2+1)*132 + lrow] = pack2(w0.z, w0.w);
        Bs2[(lk2+2)*132 + lrow] = pack2(w1.x, w1.y);
        Bs2[(lk2+3)*132 + lrow] = pack2(w1.z, w1.w);

        __syncthreads();

#pragma unroll
        for (int k2 = 0; k2 < 8; k2++) {
            u64 a2[8], b2[8];
#pragma unroll
            for (int q = 0; q < 4; q++) {
                ulonglong2 va = *(const ulonglong2*)&As2[k2*132 + tr*8 + q*2];
                a2[q*2+0] = va.x; a2[q*2+1] = va.y;
                ulonglong2 vb = *(const ulonglong2*)&Bs2[k2*132 + tc*8 + q*2];
                b2[q*2+0] = vb.x; b2[q*2+1] = vb.y;
            }
#pragma unroll
            for (int i = 0; i < 8; i++)
#pragma unroll
                for (int j = 0; j < 8; j++)
                    acc2[i][j] = ffma2(a2[i], b2[j], acc2[i][j]);
        }
        __syncthreads();
    }

    float* __restrict__ dst = (blockIdx.y == 0) ? g_Q : g_K;
#pragma unroll
    for (int i = 0; i < 8; i++) {
        int m = m0 + tr*8 + i;
        float c[8];
#pragma unroll
        for (int j = 0; j < 8; j++) {
            float lo, hi; unpack2(acc2[i][j], lo, hi);
            c[j] = lo + hi;
        }
        *(float4*)&dst[(long)m * HEAD + tc*8]     = make_float4(c[0], c[1], c[2], c[3]);
        *(float4*)&dst[(long)m * HEAD + tc*8 + 4] = make_float4(c[4], c[5], c[6], c[7]);
    }
}

// ---------------------------------------------------------------------------
// Causal flash attention: split-K(2), f32x2, cp.async double-buffered K/V.
// Smem (u64 units): Qs2[0,4096) K0[4096) K1[8192) V0[12288) V1[16384) P@20480
// ---------------------------------------------------------------------------
#define SMEM_BYTES (20480*8 + 64*66*4)   // 180736

__global__ __launch_bounds__(256) void flash_kernel()
{
    extern __shared__ u64 smu[];
    u64* Qs2 = smu;                      // [64 d2][64 s]
    u64* Kb0 = smu + 4096;
    u64* Kb1 = smu + 8192;
    u64* Vb0 = smu + 12288;              // [32 k2][128 h]
    u64* Vb1 = smu + 16384;
    float* Ps = (float*)(smu + 20480);   // [64 r][66]

    const int tid = threadIdx.x;
    const int tr = tid >> 4;   // 0..15
    const int tc = tid & 15;   // 0..15

    const int j   = blockIdx.x;
    const int qt  = 31 - (j >> 3);
    const int b   = (j >> 1) & 3;
    const int par = j & 1;

    const int nkt   = qt + 1;
    const int half  = (nkt + 1) >> 1;
    const int kt_lo = par ? half : 0;
    const int kt_hi = par ? nkt  : half;

    // Q tile: straight coalesced copy (already transposed/interleaved/scaled)
    const u64* __restrict__ Qg = g_QT2 + (long)b * 64 * SEQ + qt * 64;
    for (int c = tid; c < 4096; c += 256) {
        int d2 = c >> 6, ss = c & 63;
        Qs2[c] = Qg[(long)d2 * SEQ + ss];
    }

    u64 o2[4][8];
#pragma unroll
    for (int i = 0; i < 4; i++)
#pragma unroll
        for (int jj = 0; jj < 8; jj++) o2[i][jj] = 0ULL;
    float m_i[4] = {-1e30f, -1e30f, -1e30f, -1e30f};
    float l_i[4] = {0.f, 0.f, 0.f, 0.f};

    const u64* __restrict__ Kg = g_KT2 + (long)b * 64 * SEQ;

    // prologue prefetch of tile kt_lo into buffer 0
    if (kt_lo < kt_hi) {
        for (int c = tid; c < 2048; c += 256) {
            int d2 = c >> 5, ch = c & 31;
            cp16(Kb0 + d2*64 + ch*2, Kg + (long)d2 * SEQ + kt_lo*64 + ch*2);
        }
        const u64* Vg = g_VT2 + (long)kt_lo * 32 * HEAD;
        for (int c = tid; c < 2048; c += 256)
            cp16(Vb0 + c*2, Vg + c*2);
        CP_COMMIT();
    }

    for (int kt = kt_lo; kt < kt_hi; kt++) {
        const int buf = (kt - kt_lo) & 1;
        u64* Ks2 = buf ? Kb1 : Kb0;
        u64* Vs2 = buf ? Vb1 : Vb0;

        __syncthreads();   // everyone done with buf^1 (and Ps / Q stores on iter 0)

        if (kt + 1 < kt_hi) {
            u64* Kn = buf ? Kb0 : Kb1;
            u64* Vn = buf ? Vb0 : Vb1;
            for (int c = tid; c < 2048; c += 256) {
                int d2 = c >> 5, ch = c & 31;
                cp16(Kn + d2*64 + ch*2, Kg + (long)d2 * SEQ + (kt+1)*64 + ch*2);
            }
            const u64* Vg = g_VT2 + (long)(kt+1) * 32 * HEAD;
            for (int c = tid; c < 2048; c += 256)
                cp16(Vn + c*2, Vg + c*2);
            CP_COMMIT();
            CP_WAIT(1);
        } else {
            CP_WAIT(0);
        }
        __syncthreads();   // tile kt visible to all threads

        // ---- S = Q K^T, d-pair packed ----
        u64 s2[4][4];
#pragma unroll
        for (int i = 0; i < 4; i++)
#pragma unroll
            for (int jj = 0; jj < 4; jj++) s2[i][jj] = 0ULL;

#pragma unroll 8
        for (int d2 = 0; d2 < 64; d2++) {
            u64 a2[4], b2[4];
            ulonglong2 qa0 = *(const ulonglong2*)&Qs2[d2*64 + tr*4];
            ulonglong2 qa1 = *(const ulonglong2*)&Qs2[d2*64 + tr*4 + 2];
            a2[0]=qa0.x; a2[1]=qa0.y; a2[2]=qa1.x; a2[3]=qa1.y;
            ulonglong2 kb0 = *(const ulonglong2*)&Ks2[d2*64 + tc*4];
            ulonglong2 kb1 = *(const ulonglong2*)&Ks2[d2*64 + tc*4 + 2];
            b2[0]=kb0.x; b2[1]=kb0.y; b2[2]=kb1.x; b2[3]=kb1.y;
#pragma unroll
            for (int i = 0; i < 4; i++)
#pragma unroll
                for (int jj = 0; jj < 4; jj++)
                    s2[i][jj] = ffma2(a2[i], b2[jj], s2[i][jj]);
        }

        // ---- mask + online softmax ----
#pragma unroll
        for (int i = 0; i < 4; i++) {
            const int qrow = qt * 64 + tr * 4 + i;
            float sv[4];
            float rowmax = -1e30f;
#pragma unroll
            for (int jj = 0; jj < 4; jj++) {
                float lo, hi; unpack2(s2[i][jj], lo, hi);
                float v = lo + hi;
                int kcol = kt * 64 + tc * 4 + jj;
                v = (kcol <= qrow) ? v : -1e30f;
                sv[jj] = v;
                rowmax = fmaxf(rowmax, v);
            }
#pragma unroll
            for (int off = 8; off >= 1; off >>= 1)
                rowmax = fmaxf(rowmax, __shfl_xor_sync(0xffffffffu, rowmax, off));

            float mnew = fmaxf(m_i[i], rowmax);
            float fac  = __expf(m_i[i] - mnew);
            float psum = 0.f;
#pragma unroll
            for (int jj = 0; jj < 4; jj++) {
                float p = __expf(sv[jj] - mnew);
                Ps[(tr * 4 + i) * 66 + tc * 4 + jj] = p;
                psum += p;
            }
#pragma unroll
            for (int off = 8; off >= 1; off >>= 1)
                psum += __shfl_xor_sync(0xffffffffu, psum, off);

            l_i[i] = l_i[i] * fac + psum;
            m_i[i] = mnew;
            u64 facp = pack2(fac, fac);
#pragma unroll
            for (int jj = 0; jj < 8; jj++) o2[i][jj] = fmul2(o2[i][jj], facp);
        }
        __syncthreads();   // Ps visible

        // ---- O += P @ V, kk-pair packed ----
#pragma unroll 4
        for (int k2 = 0; k2 < 32; k2++) {
            u64 v2[8];
#pragma unroll
            for (int q = 0; q < 4; q++) {
                ulonglong2 vv = *(const ulonglong2*)&Vs2[k2*128 + tc*8 + q*2];
                v2[q*2+0] = vv.x; v2[q*2+1] = vv.y;
            }
#pragma unroll
            for (int i = 0; i < 4; i++) {
                u64 p2 = *(const u64*)&Ps[(tr * 4 + i) * 66 + k2 * 2];
#pragma unroll
                for (int jj = 0; jj < 8; jj++)
                    o2[i][jj] = ffma2(p2, v2[jj], o2[i][jj]);
            }
        }
    }

    // ---- write unnormalized partial O + (m, l) ----
    float* __restrict__ Og = g_O[par] + (long)(b * SEQ + qt * 64) * HEAD;
#pragma unroll
    for (int i = 0; i < 4; i++) {
        int r = tr * 4 + i;
        float c[8];
#pragma unroll
        for (int jj = 0; jj < 8; jj++) {
            float lo, hi; unpack2(o2[i][jj], lo, hi);
            c[jj] = lo + hi;
        }
        *(float4*)&Og[(long)r * HEAD + tc * 8]     = make_float4(c[0], c[1], c[2], c[3]);
        *(float4*)&Og[(long)r * HEAD + tc * 8 + 4] = make_float4(c[4], c[5], c[6], c[7]);
        if (tc == 0) {
            int row = b * SEQ + qt * 64 + r;
            g_m[par][row] = m_i[i];
            g_l[par][row] = l_i[i];
        }
    }
}

// ---------------------------------------------------------------------------
__global__ void combine_kernel(float* __restrict__ out)
{
    int id = blockIdx.x * 256 + threadIdx.x;
    int row = id >> 7;
    float m0 = g_m[0][row], m1 = g_m[1][row];
    float l0 = g_l[0][row], l1 = g_l[1][row];
    float m  = fmaxf(m0, m1);
    float w0 = __expf(m0 - m);
    float w1 = __expf(m1 - m);
    float denom = w0 * l0 + w1 * l1;
    out[id] = (w0 * g_O[0][id] + w1 * g_O[1][id]) / denom;
}

// ---------------------------------------------------------------------------
extern "C" void kernel_launch(void* const* d_in, const int* in_sizes, int n_in,
                              void* d_out, int out_size)
{
    const float* X  = (const float*)d_in[0];
    const float* WQ = (const float*)d_in[1];
    const float* WK = (const float*)d_in[2];
    const float* WV = (const float*)d_in[3];
    float* out = (float*)d_out;

    cudaFuncSetAttribute(flash_kernel,
                         cudaFuncAttributeMaxDynamicSharedMemorySize, SMEM_BYTES);

    repack_v_kernel<<<32, 256>>>(WV);                 // launch 0
    proj_kernel<<<dim3(64, 2), 256>>>(X, WQ, WK);     // launch 1
    repack_qk_kernel<<<dim3(256, 2), 256>>>();        // launch 2
    flash_kernel<<<BATCH * NQT * 2, 256, SMEM_BYTES>>>();  // launch 3 (ncu target)
    combine_kernel<<<(BATCH * SEQ * HEAD) / 256, 256>>>(out); // launch 4
}

// round 5
// speedup vs baseline: 2.0454x; 1.7597x over previous
#include <cuda_runtime.h>
#include <cuda_bf16.h>
#include <math.h>
#include <cstdint>

#define BATCH 4
#define SEQ   2048
#define EMB   2048
#define HEAD  128
#define NQT   (SEQ/64)

typedef unsigned long long u64;

// ------------------------- device scratch -------------------------
__device__ float g_Q[BATCH*SEQ*HEAD];
__device__ float g_K[BATCH*SEQ*HEAD];
__device__ __nv_bfloat16 g_Xhi[BATCH*SEQ*EMB];
__device__ __nv_bfloat16 g_Xlo[BATCH*SEQ*EMB];
__device__ __nv_bfloat16 g_Bhi[256*EMB];     // rows 0-127: WQ, 128-255: WK
__device__ __nv_bfloat16 g_Blo[256*EMB];
__device__ u64   g_QT2[BATCH*64*SEQ];        // [b][d2][s] pair-interleaved, scaled
__device__ u64   g_KT2[BATCH*64*SEQ];
__device__ u64   g_VT2[(SEQ/2)*HEAD];        // [k2][h] pair-interleaved V=W_V^T
__device__ float g_O[2][BATCH*SEQ*HEAD];
__device__ float g_m[2][BATCH*SEQ];
__device__ float g_l[2][BATCH*SEQ];

// ------------------------- f32x2 helpers -------------------------
__device__ __forceinline__ u64 pack2(float lo, float hi) {
    u64 r; asm("mov.b64 %0, {%1, %2};" : "=l"(r) : "f"(lo), "f"(hi)); return r;
}
__device__ __forceinline__ void unpack2(u64 v, float& lo, float& hi) {
    asm("mov.b64 {%0, %1}, %2;" : "=f"(lo), "=f"(hi) : "l"(v));
}
__device__ __forceinline__ u64 ffma2(u64 a, u64 b, u64 c) {
    u64 d; asm("fma.rn.f32x2 %0, %1, %2, %3;" : "=l"(d) : "l"(a), "l"(b), "l"(c)); return d;
}
__device__ __forceinline__ u64 fmul2(u64 a, u64 b) {
    u64 d; asm("mul.rn.f32x2 %0, %1, %2;" : "=l"(d) : "l"(a), "l"(b)); return d;
}

// ------------------------- cp.async helpers -------------------------
__device__ __forceinline__ void cp16(void* smem_dst, const void* gsrc) {
    unsigned sd = (unsigned)__cvta_generic_to_shared(smem_dst);
    asm volatile("cp.async.cg.shared.global [%0], [%1], 16;\n" :: "r"(sd), "l"(gsrc));
}
__device__ __forceinline__ void cp16s(unsigned sd, const void* gsrc) {
    asm volatile("cp.async.cg.shared.global [%0], [%1], 16;\n" :: "r"(sd), "l"(gsrc));
}
#define CP_COMMIT() asm volatile("cp.async.commit_group;\n" ::: "memory")
#define CP_WAIT(N)  asm volatile("cp.async.wait_group %0;\n" :: "n"(N) : "memory")

__device__ __forceinline__ unsigned smem_u32(const void* p) {
    return (unsigned)__cvta_generic_to_shared((void*)p);
}

// ------------------------- mma.sync helpers -------------------------
__device__ __forceinline__ void ldsm_x4(unsigned addr, unsigned& r0, unsigned& r1,
                                        unsigned& r2, unsigned& r3) {
    asm volatile("ldmatrix.sync.aligned.m8n8.x4.shared.b16 {%0,%1,%2,%3}, [%4];"
                 : "=r"(r0), "=r"(r1), "=r"(r2), "=r"(r3) : "r"(addr));
}
__device__ __forceinline__ void mma_bf16(float* c, const unsigned* a, const unsigned* b) {
    asm volatile(
        "mma.sync.aligned.m16n8k16.row.col.f32.bf16.bf16.f32 "
        "{%0,%1,%2,%3}, {%4,%5,%6,%7}, {%8,%9}, {%0,%1,%2,%3};"
        : "+f"(c[0]), "+f"(c[1]), "+f"(c[2]), "+f"(c[3])
        : "r"(a[0]), "r"(a[1]), "r"(a[2]), "r"(a[3]), "r"(b[0]), "r"(b[1]));
}

// ---------------------------------------------------------------------------
// convert X -> (hi, lo) bf16 split
// ---------------------------------------------------------------------------
__global__ __launch_bounds__(256) void convert_x_kernel(const float* __restrict__ X)
{
    long i = ((long)blockIdx.x * 256 + threadIdx.x) * 4;
    float4 v = *(const float4*)(X + i);
    float vv[4] = {v.x, v.y, v.z, v.w};
    __nv_bfloat16 hi[4], lo[4];
#pragma unroll
    for (int q = 0; q < 4; q++) {
        hi[q] = __float2bfloat16(vv[q]);
        lo[q] = __float2bfloat16(vv[q] - __bfloat162float(hi[q]));
    }
    *(ushort4*)&g_Xhi[i] = *(ushort4*)hi;
    *(ushort4*)&g_Xlo[i] = *(ushort4*)lo;
}

// ---------------------------------------------------------------------------
// convert W (WQ rows 0-127, WK rows 128-255) -> (hi, lo) bf16
// ---------------------------------------------------------------------------
__global__ __launch_bounds__(256) void convert_w_kernel(
    const float* __restrict__ WQ, const float* __restrict__ WK)
{
    long i = ((long)blockIdx.x * 256 + threadIdx.x) * 4;
    int r = (int)(i >> 11);
    long c = i & 2047;
    const float* src = (r < 128) ? (WQ + (long)r * EMB + c) : (WK + (long)(r - 128) * EMB + c);
    float4 v = *(const float4*)src;
    float vv[4] = {v.x, v.y, v.z, v.w};
    __nv_bfloat16 hi[4], lo[4];
#pragma unroll
    for (int q = 0; q < 4; q++) {
        hi[q] = __float2bfloat16(vv[q]);
        lo[q] = __float2bfloat16(vv[q] - __bfloat162float(hi[q]));
    }
    *(ushort4*)&g_Bhi[i] = *(ushort4*)hi;
    *(ushort4*)&g_Blo[i] = *(ushort4*)lo;
}

// ---------------------------------------------------------------------------
// Repack V: WV[128,2048] -> g_VT2[k2][h] pair-interleaved.
// ---------------------------------------------------------------------------
__global__ __launch_bounds__(256) void repack_v_kernel(const float* __restrict__ WV)
{
    __shared__ float t[128][66];
    const int tid = threadIdx.x;
    const int k0  = blockIdx.x * 64;

    for (int i = tid; i < 128 * 64; i += 256) {
        int h = i >> 6, kk = i & 63;
        t[h][kk] = WV[h * EMB + k0 + kk];
    }
    __syncthreads();
    for (int j = tid; j < 32 * 128; j += 256) {
        int k2l = j >> 7, h = j & 127;
        g_VT2[((k0 >> 1) + k2l) * HEAD + h] = pack2(t[h][2*k2l], t[h][2*k2l + 1]);
    }
}

// ---------------------------------------------------------------------------
// Repack Q/K: [b][s][h] -> [b][d2][s] pair-interleaved (Q pre-scaled)
// ---------------------------------------------------------------------------
__global__ __launch_bounds__(256) void repack_qk_kernel()
{
    __shared__ float t[32][130];
    const int tid = threadIdx.x;
    const int b   = blockIdx.x >> 6;
    const int s0  = (blockIdx.x & 63) * 32;
    const int isK = blockIdx.y;

    const float* __restrict__ src = isK ? g_K : g_Q;
    u64* __restrict__ dst = isK ? g_KT2 : g_QT2;
    const float scl = isK ? 1.0f : 0.08838834764831845f;

    for (int i = tid; i < 32 * 128; i += 256) {
        int ss = i >> 7, h = i & 127;
        t[ss][h] = src[((long)(b * SEQ) + s0 + ss) * HEAD + h] * scl;
    }
    __syncthreads();
    for (int j = tid; j < 64 * 32; j += 256) {
        int d2 = j >> 5, ss = j & 31;
        dst[((long)(b * 64) + d2) * SEQ + s0 + ss] = pack2(t[ss][2*d2], t[ss][2*d2 + 1]);
    }
}

// ---------------------------------------------------------------------------
// mma.sync projection GEMM: [g_Q | g_K](8192 x 256) = X @ B^T (bf16x3 split)
// CTA 128x128 (grid 64 x 2), BK=32, double-buffered cp.async, 8 warps (4m x 2n)
// smem row stride 40 bf16 = 80 bytes (16B-aligned, ldmatrix conflict-free)
// ---------------------------------------------------------------------------
#define PJ_LDS   40            // bf16 per smem row
#define PJ_ROWB  (PJ_LDS*2)    // 80 bytes
#define PJ_ARR   (128*PJ_ROWB) // 10240 bytes per tile array
#define PJ_BUF   (4*PJ_ARR)    // A_hi A_lo B_hi B_lo
#define PJ_SMEM  (2*PJ_BUF)    // 81920 bytes

__global__ __launch_bounds__(256) void proj_mma_kernel()
{
    extern __shared__ unsigned char dsm8[];
    const unsigned sb = smem_u32(dsm8);

    const int tid = threadIdx.x;
    const int wid = tid >> 5;
    const int lane = tid & 31;
    const int wm = wid & 3;        // warp row: 0..3 (32 rows each)
    const int wn = wid >> 2;       // warp col: 0..1 (64 cols each)

    const int m0 = blockIdx.x * 128;
    const int nt = blockIdx.y;     // 0 -> g_Q, 1 -> g_K

    float acc[2][8][4];
#pragma unroll
    for (int m = 0; m < 2; m++)
#pragma unroll
        for (int n = 0; n < 8; n++)
#pragma unroll
            for (int q = 0; q < 4; q++) acc[m][n][q] = 0.f;

    // ---- cp.async tile loader: arrays {A_hi, A_lo, B_hi, B_lo} ----
    auto load_tile = [&](int buf, int kt) {
        const unsigned base = sb + buf * PJ_BUF;
        const long kof = (long)kt * 32;
        // A: 128 rows x 32 bf16 (4 x 16B chunks)
        for (int c = tid; c < 512; c += 256) {
            int r = c >> 2, ch = c & 3;
            unsigned so = (unsigned)(r * PJ_ROWB + ch * 16);
            const long gix = (long)(m0 + r) * EMB + kof + ch * 8;
            cp16s(base + so,          g_Xhi + gix);
            cp16s(base + PJ_ARR + so, g_Xlo + gix);
        }
        // B: 128 rows x 32 bf16
        for (int c = tid; c < 512; c += 256) {
            int r = c >> 2, ch = c & 3;
            unsigned so = (unsigned)(r * PJ_ROWB + ch * 16);
            const long gix = (long)(nt * 128 + r) * EMB + kof + ch * 8;
            cp16s(base + 2*PJ_ARR + so, g_Bhi + gix);
            cp16s(base + 3*PJ_ARR + so, g_Blo + gix);
        }
        CP_COMMIT();
    };

    load_tile(0, 0);

    // per-lane ldmatrix address pieces
    const int a_row_off = (lane & 7) + ((lane >> 3) & 1) * 8;  // within 16-row frag
    const int a_kb_off  = (lane >> 4) * 8;                     // 0 or 8
    const int b_n_off   = (lane & 7) + ((lane >> 3) >> 1) * 8; // tile>>1
    const int b_k_off   = ((lane >> 3) & 1) * 8;               // tile&1

    for (int kt = 0; kt < 64; kt++) {
        const int buf = kt & 1;
        __syncthreads();   // previous compute done with buf (safe to overwrite later)

        if (kt + 1 < 64) {
            load_tile(buf ^ 1, kt + 1);
            CP_WAIT(1);
        } else {
            CP_WAIT(0);
        }
        __syncthreads();

        const unsigned aH = sb + buf * PJ_BUF;
        const unsigned aL = aH + PJ_ARR;
        const unsigned bH = aH + 2*PJ_ARR;
        const unsigned bL = aH + 3*PJ_ARR;

#pragma unroll
        for (int kf = 0; kf < 2; kf++) {
            const int kb = kf * 16;
            unsigned ah[2][4], al[2][4];
#pragma unroll
            for (int m = 0; m < 2; m++) {
                unsigned row = (unsigned)(wm * 32 + m * 16 + a_row_off);
                unsigned col = (unsigned)(kb + a_kb_off);
                unsigned off = row * PJ_ROWB + col * 2;
                ldsm_x4(aH + off, ah[m][0], ah[m][1], ah[m][2], ah[m][3]);
                ldsm_x4(aL + off, al[m][0], al[m][1], al[m][2], al[m][3]);
            }
            unsigned bh[8][2], bl[8][2];
#pragma unroll
            for (int g = 0; g < 4; g++) {
                unsigned nrow = (unsigned)(wn * 64 + g * 16 + b_n_off);
                unsigned kcol = (unsigned)(kb + b_k_off);
                unsigned off = nrow * PJ_ROWB + kcol * 2;
                ldsm_x4(bH + off, bh[g*2][0], bh[g*2][1], bh[g*2+1][0], bh[g*2+1][1]);
                ldsm_x4(bL + off, bl[g*2][0], bl[g*2][1], bl[g*2+1][0], bl[g*2+1][1]);
            }
#pragma unroll
            for (int m = 0; m < 2; m++)
#pragma unroll
                for (int n = 0; n < 8; n++) {
                    mma_bf16(acc[m][n], ah[m], bh[n]);
                    mma_bf16(acc[m][n], ah[m], bl[n]);
                    mma_bf16(acc[m][n], al[m], bh[n]);
                }
        }
    }

    // ---- epilogue: write g_Q / g_K ----
    float* __restrict__ dst = nt ? g_K : g_Q;
#pragma unroll
    for (int m = 0; m < 2; m++) {
        const int row = m0 + wm * 32 + m * 16 + (lane >> 2);
#pragma unroll
        for (int n = 0; n < 8; n++) {
            const int col = wn * 64 + n * 8 + (lane & 3) * 2;
            *(float2*)&dst[(long)row * HEAD + col] =
                make_float2(acc[m][n][0], acc[m][n][1]);
            *(float2*)&dst[(long)(row + 8) * HEAD + col] =
                make_float2(acc[m][n][2], acc[m][n][3]);
        }
    }
}

// ---------------------------------------------------------------------------
// Causal flash attention: split-K(2), f32x2, cp.async double-buffered K/V.
// ---------------------------------------------------------------------------
#define SMEM_BYTES (20480*8 + 64*66*4)   // 180736

__global__ __launch_bounds__(256) void flash_kernel()
{
    extern __shared__ unsigned char dsm8[];
    u64* smu = (u64*)dsm8;
    u64* Qs2 = smu;                      // [64 d2][64 s]
    u64* Kb0 = smu + 4096;
    u64* Kb1 = smu + 8192;
    u64* Vb0 = smu + 12288;              // [32 k2][128 h]
    u64* Vb1 = smu + 16384;
    float* Ps = (float*)(smu + 20480);   // [64 r][66]

    const int tid = threadIdx.x;
    const int tr = tid >> 4;
    const int tc = tid & 15;

    const int j   = blockIdx.x;
    const int qt  = 31 - (j >> 3);
    const int b   = (j >> 1) & 3;
    const int par = j & 1;

    const int nkt   = qt + 1;
    const int half  = (nkt + 1) >> 1;
    const int kt_lo = par ? half : 0;
    const int kt_hi = par ? nkt  : half;

    const u64* __restrict__ Qg = g_QT2 + (long)b * 64 * SEQ + qt * 64;
    for (int c = tid; c < 4096; c += 256) {
        int d2 = c >> 6, ss = c & 63;
        Qs2[c] = Qg[(long)d2 * SEQ + ss];
    }

    u64 o2[4][8];
#pragma unroll
    for (int i = 0; i < 4; i++)
#pragma unroll
        for (int jj = 0; jj < 8; jj++) o2[i][jj] = 0ULL;
    float m_i[4] = {-1e30f, -1e30f, -1e30f, -1e30f};
    float l_i[4] = {0.f, 0.f, 0.f, 0.f};

    const u64* __restrict__ Kg = g_KT2 + (long)b * 64 * SEQ;

    if (kt_lo < kt_hi) {
        for (int c = tid; c < 2048; c += 256) {
            int d2 = c >> 5, ch = c & 31;
            cp16(Kb0 + d2*64 + ch*2, Kg + (long)d2 * SEQ + kt_lo*64 + ch*2);
        }
        const u64* Vg = g_VT2 + (long)kt_lo * 32 * HEAD;
        for (int c = tid; c < 2048; c += 256)
            cp16(Vb0 + c*2, Vg + c*2);
        CP_COMMIT();
    }

    for (int kt = kt_lo; kt < kt_hi; kt++) {
        const int buf = (kt - kt_lo) & 1;
        u64* Ks2 = buf ? Kb1 : Kb0;
        u64* Vs2 = buf ? Vb1 : Vb0;

        __syncthreads();

        if (kt + 1 < kt_hi) {
            u64* Kn = buf ? Kb0 : Kb1;
            u64* Vn = buf ? Vb0 : Vb1;
            for (int c = tid; c < 2048; c += 256) {
                int d2 = c >> 5, ch = c & 31;
                cp16(Kn + d2*64 + ch*2, Kg + (long)d2 * SEQ + (kt+1)*64 + ch*2);
            }
            const u64* Vg = g_VT2 + (long)(kt+1) * 32 * HEAD;
            for (int c = tid; c < 2048; c += 256)
                cp16(Vn + c*2, Vg + c*2);
            CP_COMMIT();
            CP_WAIT(1);
        } else {
            CP_WAIT(0);
        }
        __syncthreads();

        u64 s2[4][4];
#pragma unroll
        for (int i = 0; i < 4; i++)
#pragma unroll
            for (int jj = 0; jj < 4; jj++) s2[i][jj] = 0ULL;

#pragma unroll 8
        for (int d2 = 0; d2 < 64; d2++) {
            u64 a2[4], b2[4];
            ulonglong2 qa0 = *(const ulonglong2*)&Qs2[d2*64 + tr*4];
            ulonglong2 qa1 = *(const ulonglong2*)&Qs2[d2*64 + tr*4 + 2];
            a2[0]=qa0.x; a2[1]=qa0.y; a2[2]=qa1.x; a2[3]=qa1.y;
            ulonglong2 kb0 = *(const ulonglong2*)&Ks2[d2*64 + tc*4];
            ulonglong2 kb1 = *(const ulonglong2*)&Ks2[d2*64 + tc*4 + 2];
            b2[0]=kb0.x; b2[1]=kb0.y; b2[2]=kb1.x; b2[3]=kb1.y;
#pragma unroll
            for (int i = 0; i < 4; i++)
#pragma unroll
                for (int jj = 0; jj < 4; jj++)
                    s2[i][jj] = ffma2(a2[i], b2[jj], s2[i][jj]);
        }

#pragma unroll
        for (int i = 0; i < 4; i++) {
            const int qrow = qt * 64 + tr * 4 + i;
            float sv[4];
            float rowmax = -1e30f;
#pragma unroll
            for (int jj = 0; jj < 4; jj++) {
                float lo, hi; unpack2(s2[i][jj], lo, hi);
                float v = lo + hi;
                int kcol = kt * 64 + tc * 4 + jj;
                v = (kcol <= qrow) ? v : -1e30f;
                sv[jj] = v;
                rowmax = fmaxf(rowmax, v);
            }
#pragma unroll
            for (int off = 8; off >= 1; off >>= 1)
                rowmax = fmaxf(rowmax, __shfl_xor_sync(0xffffffffu, rowmax, off));

            float mnew = fmaxf(m_i[i], rowmax);
            float fac  = __expf(m_i[i] - mnew);
            float psum = 0.f;
#pragma unroll
            for (int jj = 0; jj < 4; jj++) {
                float p = __expf(sv[jj] - mnew);
                Ps[(tr * 4 + i) * 66 + tc * 4 + jj] = p;
                psum += p;
            }
#pragma unroll
            for (int off = 8; off >= 1; off >>= 1)
                psum += __shfl_xor_sync(0xffffffffu, psum, off);

            l_i[i] = l_i[i] * fac + psum;
            m_i[i] = mnew;
            u64 facp = pack2(fac, fac);
#pragma unroll
            for (int jj = 0; jj < 8; jj++) o2[i][jj] = fmul2(o2[i][jj], facp);
        }
        __syncthreads();

#pragma unroll 4
        for (int k2 = 0; k2 < 32; k2++) {
            u64 v2[8];
#pragma unroll
            for (int q = 0; q < 4; q++) {
                ulonglong2 vv = *(const ulonglong2*)&Vs2[k2*128 + tc*8 + q*2];
                v2[q*2+0] = vv.x; v2[q*2+1] = vv.y;
            }
#pragma unroll
            for (int i = 0; i < 4; i++) {
                u64 p2 = *(const u64*)&Ps[(tr * 4 + i) * 66 + k2 * 2];
#pragma unroll
                for (int jj = 0; jj < 8; jj++)
                    o2[i][jj] = ffma2(p2, v2[jj], o2[i][jj]);
            }
        }
    }

    float* __restrict__ Og = g_O[par] + (long)(b * SEQ + qt * 64) * HEAD;
#pragma unroll
    for (int i = 0; i < 4; i++) {
        int r = tr * 4 + i;
        float c[8];
#pragma unroll
        for (int jj = 0; jj < 8; jj++) {
            float lo, hi; unpack2(o2[i][jj], lo, hi);
            c[jj] = lo + hi;
        }
        *(float4*)&Og[(long)r * HEAD + tc * 8]     = make_float4(c[0], c[1], c[2], c[3]);
        *(float4*)&Og[(long)r * HEAD + tc * 8 + 4] = make_float4(c[4], c[5], c[6], c[7]);
        if (tc == 0) {
            int row = b * SEQ + qt * 64 + r;
            g_m[par][row] = m_i[i];
            g_l[par][row] = l_i[i];
        }
    }
}

// ---------------------------------------------------------------------------
__global__ void combine_kernel(float* __restrict__ out)
{
    int id = blockIdx.x * 256 + threadIdx.x;
    int row = id >> 7;
    float m0 = g_m[0][row], m1 = g_m[1][row];
    float l0 = g_l[0][row], l1 = g_l[1][row];
    float m  = fmaxf(m0, m1);
    float w0 = __expf(m0 - m);
    float w1 = __expf(m1 - m);
    float denom = w0 * l0 + w1 * l1;
    out[id] = (w0 * g_O[0][id] + w1 * g_O[1][id]) / denom;
}

// ---------------------------------------------------------------------------
extern "C" void kernel_launch(void* const* d_in, const int* in_sizes, int n_in,
                              void* d_out, int out_size)
{
    const float* X  = (const float*)d_in[0];
    const float* WQ = (const float*)d_in[1];
    const float* WK = (const float*)d_in[2];
    const float* WV = (const float*)d_in[3];
    float* out = (float*)d_out;

    cudaFuncSetAttribute(flash_kernel,
                         cudaFuncAttributeMaxDynamicSharedMemorySize, SMEM_BYTES);
    cudaFuncSetAttribute(proj_mma_kernel,
                         cudaFuncAttributeMaxDynamicSharedMemorySize, PJ_SMEM);

    convert_x_kernel<<<(BATCH*SEQ*EMB)/1024, 256>>>(X);
    convert_w_kernel<<<(256*EMB)/1024, 256>>>(WQ, WK);
    repack_v_kernel<<<32, 256>>>(WV);
    proj_mma_kernel<<<dim3(64, 2), 256, PJ_SMEM>>>();
    repack_qk_kernel<<<dim3(256, 2), 256>>>();
    flash_kernel<<<BATCH * NQT * 2, 256, SMEM_BYTES>>>();
    combine_kernel<<<(BATCH * SEQ * HEAD) / 256, 256>>>(out);
}

// round 6
// speedup vs baseline: 4.5492x; 2.2241x over previous
#include <cuda_runtime.h>
#include <cuda_bf16.h>
#include <math.h>
#include <cstdint>

#define BATCH 4
#define SEQ   2048
#define EMB   2048
#define HEAD  128
#define NSPLIT 4

// ------------------------- device scratch -------------------------
__device__ __nv_bfloat16 g_Xhi[BATCH*SEQ*EMB];
__device__ __nv_bfloat16 g_Xlo[BATCH*SEQ*EMB];
__device__ __nv_bfloat16 g_Bhi[256*EMB];     // rows 0-127: WQ, 128-255: WK
__device__ __nv_bfloat16 g_Blo[256*EMB];
__device__ __nv_bfloat16 g_Vhi[HEAD*EMB];    // W_V as-is: [h][k]
__device__ __nv_bfloat16 g_Vlo[HEAD*EMB];
__device__ __nv_bfloat16 g_Qhi[BATCH*SEQ*HEAD];  // pre-scaled by 1/sqrt(128)
__device__ __nv_bfloat16 g_Qlo[BATCH*SEQ*HEAD];
__device__ __nv_bfloat16 g_Khi[BATCH*SEQ*HEAD];
__device__ __nv_bfloat16 g_Klo[BATCH*SEQ*HEAD];
__device__ float g_O[NSPLIT][BATCH*SEQ*HEAD];    // unnormalized partial O
__device__ float g_m[NSPLIT][BATCH*SEQ];
__device__ float g_l[NSPLIT][BATCH*SEQ];

// ------------------------- helpers -------------------------
__device__ __forceinline__ void cp16s(unsigned sd, const void* gsrc) {
    asm volatile("cp.async.cg.shared.global [%0], [%1], 16;\n" :: "r"(sd), "l"(gsrc));
}
#define CP_COMMIT() asm volatile("cp.async.commit_group;\n" ::: "memory")
#define CP_WAIT(N)  asm volatile("cp.async.wait_group %0;\n" :: "n"(N) : "memory")

__device__ __forceinline__ unsigned smem_u32(const void* p) {
    return (unsigned)__cvta_generic_to_shared((void*)p);
}
__device__ __forceinline__ void ldsm_x4(unsigned addr, unsigned& r0, unsigned& r1,
                                        unsigned& r2, unsigned& r3) {
    asm volatile("ldmatrix.sync.aligned.m8n8.x4.shared.b16 {%0,%1,%2,%3}, [%4];"
                 : "=r"(r0), "=r"(r1), "=r"(r2), "=r"(r3) : "r"(addr));
}
__device__ __forceinline__ void mma_bf16(float* c, const unsigned* a, const unsigned* b) {
    asm volatile(
        "mma.sync.aligned.m16n8k16.row.col.f32.bf16.bf16.f32 "
        "{%0,%1,%2,%3}, {%4,%5,%6,%7}, {%8,%9}, {%0,%1,%2,%3};"
        : "+f"(c[0]), "+f"(c[1]), "+f"(c[2]), "+f"(c[3])
        : "r"(a[0]), "r"(a[1]), "r"(a[2]), "r"(a[3]), "r"(b[0]), "r"(b[1]));
}
// pack two f32 -> bf16x2 (lo_val in low 16 bits)
__device__ __forceinline__ unsigned cvt2_bf16(float lo_val, float hi_val) {
    unsigned r;
    asm("cvt.rn.bf16x2.f32 %0, %1, %2;" : "=r"(r) : "f"(hi_val), "f"(lo_val));
    return r;
}
__device__ __forceinline__ float bf16_round(float x) {
    return __bfloat162float(__float2bfloat16(x));
}

// ---------------------------------------------------------------------------
// convert X -> (hi, lo) bf16 split
// ---------------------------------------------------------------------------
__global__ __launch_bounds__(256) void convert_x_kernel(const float* __restrict__ X)
{
    long i = ((long)blockIdx.x * 256 + threadIdx.x) * 4;
    float4 v = *(const float4*)(X + i);
    float vv[4] = {v.x, v.y, v.z, v.w};
    __nv_bfloat16 hi[4], lo[4];
#pragma unroll
    for (int q = 0; q < 4; q++) {
        hi[q] = __float2bfloat16(vv[q]);
        lo[q] = __float2bfloat16(vv[q] - __bfloat162float(hi[q]));
    }
    *(ushort4*)&g_Xhi[i] = *(ushort4*)hi;
    *(ushort4*)&g_Xlo[i] = *(ushort4*)lo;
}

// ---------------------------------------------------------------------------
// convert WQ/WK (rows 0-255 -> g_B*) and WV (-> g_V*) in one kernel
// ---------------------------------------------------------------------------
__global__ __launch_bounds__(256) void convert_wv_kernel(
    const float* __restrict__ WQ, const float* __restrict__ WK,
    const float* __restrict__ WV)
{
    long i = ((long)blockIdx.x * 256 + threadIdx.x) * 4;
    const float* src;
    __nv_bfloat16 *dhi, *dlo;
    long didx;
    if (i < 256L * EMB) {
        int r = (int)(i >> 11);
        long c = i & 2047;
        src = (r < 128) ? (WQ + (long)r * EMB + c) : (WK + (long)(r - 128) * EMB + c);
        dhi = g_Bhi; dlo = g_Blo; didx = i;
    } else {
        long j = i - 256L * EMB;
        src = WV + j;
        dhi = g_Vhi; dlo = g_Vlo; didx = j;
    }
    float4 v = *(const float4*)src;
    float vv[4] = {v.x, v.y, v.z, v.w};
    __nv_bfloat16 hi[4], lo[4];
#pragma unroll
    for (int q = 0; q < 4; q++) {
        hi[q] = __float2bfloat16(vv[q]);
        lo[q] = __float2bfloat16(vv[q] - __bfloat162float(hi[q]));
    }
    *(ushort4*)&dhi[didx] = *(ushort4*)hi;
    *(ushort4*)&dlo[didx] = *(ushort4*)lo;
}

// ---------------------------------------------------------------------------
// mma.sync projection GEMM: Q/K(8192 x 128 each) = X @ B^T (bf16x3 split)
// CTA 128x128 (grid 64 x 2), BK=32, double-buffered cp.async, 8 warps (4m x 2n)
// Epilogue emits bf16 hi/lo (Q pre-scaled by 1/sqrt(128)).
// ---------------------------------------------------------------------------
#define PJ_LDS   40
#define PJ_ROWB  (PJ_LDS*2)
#define PJ_ARR   (128*PJ_ROWB)
#define PJ_BUF   (4*PJ_ARR)
#define PJ_SMEM  (2*PJ_BUF)

__global__ __launch_bounds__(256) void proj_mma_kernel()
{
    extern __shared__ unsigned char dsm8[];
    const unsigned sb = smem_u32(dsm8);

    const int tid = threadIdx.x;
    const int wid = tid >> 5;
    const int lane = tid & 31;
    const int wm = wid & 3;
    const int wn = wid >> 2;

    const int m0 = blockIdx.x * 128;
    const int nt = blockIdx.y;     // 0 -> Q, 1 -> K

    float acc[2][8][4];
#pragma unroll
    for (int m = 0; m < 2; m++)
#pragma unroll
        for (int n = 0; n < 8; n++)
#pragma unroll
            for (int q = 0; q < 4; q++) acc[m][n][q] = 0.f;

    auto load_tile = [&](int buf, int kt) {
        const unsigned base = sb + buf * PJ_BUF;
        const long kof = (long)kt * 32;
        for (int c = tid; c < 512; c += 256) {
            int r = c >> 2, ch = c & 3;
            unsigned so = (unsigned)(r * PJ_ROWB + ch * 16);
            const long gix = (long)(m0 + r) * EMB + kof + ch * 8;
            cp16s(base + so,          g_Xhi + gix);
            cp16s(base + PJ_ARR + so, g_Xlo + gix);
        }
        for (int c = tid; c < 512; c += 256) {
            int r = c >> 2, ch = c & 3;
            unsigned so = (unsigned)(r * PJ_ROWB + ch * 16);
            const long gix = (long)(nt * 128 + r) * EMB + kof + ch * 8;
            cp16s(base + 2*PJ_ARR + so, g_Bhi + gix);
            cp16s(base + 3*PJ_ARR + so, g_Blo + gix);
        }
        CP_COMMIT();
    };

    load_tile(0, 0);

    const int a_row_off = (lane & 7) + ((lane >> 3) & 1) * 8;
    const int a_kb_off  = (lane >> 4) * 8;
    const int b_n_off   = (lane & 7) + ((lane >> 3) >> 1) * 8;
    const int b_k_off   = ((lane >> 3) & 1) * 8;

    for (int kt = 0; kt < 64; kt++) {
        const int buf = kt & 1;
        __syncthreads();

        if (kt + 1 < 64) {
            load_tile(buf ^ 1, kt + 1);
            CP_WAIT(1);
        } else {
            CP_WAIT(0);
        }
        __syncthreads();

        const unsigned aH = sb + buf * PJ_BUF;
        const unsigned aL = aH + PJ_ARR;
        const unsigned bH = aH + 2*PJ_ARR;
        const unsigned bL = aH + 3*PJ_ARR;

#pragma unroll
        for (int kf = 0; kf < 2; kf++) {
            const int kb = kf * 16;
            unsigned ah[2][4], al[2][4];
#pragma unroll
            for (int m = 0; m < 2; m++) {
                unsigned row = (unsigned)(wm * 32 + m * 16 + a_row_off);
                unsigned col = (unsigned)(kb + a_kb_off);
                unsigned off = row * PJ_ROWB + col * 2;
                ldsm_x4(aH + off, ah[m][0], ah[m][1], ah[m][2], ah[m][3]);
                ldsm_x4(aL + off, al[m][0], al[m][1], al[m][2], al[m][3]);
            }
            unsigned bh[8][2], bl[8][2];
#pragma unroll
            for (int g = 0; g < 4; g++) {
                unsigned nrow = (unsigned)(wn * 64 + g * 16 + b_n_off);
                unsigned kcol = (unsigned)(kb + b_k_off);
                unsigned off = nrow * PJ_ROWB + kcol * 2;
                ldsm_x4(bH + off, bh[g*2][0], bh[g*2][1], bh[g*2+1][0], bh[g*2+1][1]);
                ldsm_x4(bL + off, bl[g*2][0], bl[g*2][1], bl[g*2+1][0], bl[g*2+1][1]);
            }
#pragma unroll
            for (int m = 0; m < 2; m++)
#pragma unroll
                for (int n = 0; n < 8; n++) {
                    mma_bf16(acc[m][n], ah[m], bh[n]);
                    mma_bf16(acc[m][n], ah[m], bl[n]);
                    mma_bf16(acc[m][n], al[m], bh[n]);
                }
        }
    }

    // ---- epilogue: write bf16 hi/lo (Q pre-scaled) ----
    __nv_bfloat16* __restrict__ dhi = nt ? g_Khi : g_Qhi;
    __nv_bfloat16* __restrict__ dlo = nt ? g_Klo : g_Qlo;
    const float scl = nt ? 1.0f : 0.08838834764831845f;
#pragma unroll
    for (int m = 0; m < 2; m++) {
        const int row = m0 + wm * 32 + m * 16 + (lane >> 2);
#pragma unroll
        for (int n = 0; n < 8; n++) {
            const int col = wn * 64 + n * 8 + (lane & 3) * 2;
            float v0 = acc[m][n][0] * scl, v1 = acc[m][n][1] * scl;
            float v2 = acc[m][n][2] * scl, v3 = acc[m][n][3] * scl;
            *(unsigned*)&dhi[(long)row * HEAD + col] = cvt2_bf16(v0, v1);
            *(unsigned*)&dlo[(long)row * HEAD + col] =
                cvt2_bf16(v0 - bf16_round(v0), v1 - bf16_round(v1));
            *(unsigned*)&dhi[(long)(row + 8) * HEAD + col] = cvt2_bf16(v2, v3);
            *(unsigned*)&dlo[(long)(row + 8) * HEAD + col] =
                cvt2_bf16(v2 - bf16_round(v2), v3 - bf16_round(v3));
        }
    }
}

// ---------------------------------------------------------------------------
// Tensor-core causal flash attention, bf16x3 split, split-K(4).
// CTA: 128 q-rows x 64 k-tile, 8 warps (16 rows each). Double-buffered K/V.
// smem: QH 0 (34816) QL 34816 | K bufs @69632 (2 x {H:17408, L:17408})
//       V bufs @139264 (2 x {H:18432, L:18432}) ; total 212992 B
// ---------------------------------------------------------------------------
#define FL_QROWB 272
#define FL_KROWB 272
#define FL_VROWB 144
#define FL_QH 0
#define FL_QL 34816
#define FL_KB 69632
#define FL_VB 139264
#define FL_SMEM 212992

__global__ __launch_bounds__(256) void flash_kernel()
{
    extern __shared__ unsigned char dsm8[];
    const unsigned sb = smem_u32(dsm8);

    const int tid = threadIdx.x;
    const int wm  = tid >> 5;      // warp = row stripe 0..7
    const int lane = tid & 31;

    const int bid = blockIdx.x;
    const int qt = 15 - (bid >> 4);        // heavy-first
    const int b  = (bid >> 2) & 3;
    const int sp = bid & 3;

    const int nkt   = 2 * (qt + 1);
    const int chunk = (nkt + NSPLIT - 1) / NSPLIT;
    const int kt_lo = sp * chunk;
    const int kt_hi = min(nkt, kt_lo + chunk);

    const long qrow0 = (long)b * SEQ + qt * 128;

    // ---- Q tile load (once) ----
    for (int c = tid; c < 2048; c += 256) {
        int r = c >> 4, ch = c & 15;
        unsigned so = (unsigned)(r * FL_QROWB + ch * 16);
        const long gix = (qrow0 + r) * HEAD + ch * 8;
        cp16s(sb + FL_QH + so, g_Qhi + gix);
        cp16s(sb + FL_QL + so, g_Qlo + gix);
    }

    auto load_kv = [&](int buf, int kt) {
        const unsigned kh = sb + FL_KB + buf * 34816;
        const unsigned vh = sb + FL_VB + buf * 36864;
        for (int c = tid; c < 1024; c += 256) {
            int r = c >> 4, ch = c & 15;
            unsigned so = (unsigned)(r * FL_KROWB + ch * 16);
            const long gix = ((long)b * SEQ + kt * 64 + r) * HEAD + ch * 8;
            cp16s(kh + so,         g_Khi + gix);
            cp16s(kh + 17408 + so, g_Klo + gix);
        }
        for (int c = tid; c < 1024; c += 256) {
            int r = c >> 3, ch = c & 7;
            unsigned so = (unsigned)(r * FL_VROWB + ch * 16);
            const long gix = (long)r * EMB + kt * 64 + ch * 8;
            cp16s(vh + so,         g_Vhi + gix);
            cp16s(vh + 18432 + so, g_Vlo + gix);
        }
        CP_COMMIT();
    };

    if (kt_lo < kt_hi) load_kv(0, kt_lo);
    else CP_COMMIT();   // pair the Q loads into a group anyway

    float o[16][4];
#pragma unroll
    for (int n = 0; n < 16; n++)
#pragma unroll
        for (int q = 0; q < 4; q++) o[n][q] = 0.f;
    float m0 = -1e30f, m1 = -1e30f;
    float l0 = 0.f, l1 = 0.f;

    const int a_row_off = (lane & 7) + ((lane >> 3) & 1) * 8;
    const int a_kb_off  = (lane >> 4) * 8;
    const int b_n_off   = (lane & 7) + ((lane >> 3) >> 1) * 8;
    const int b_k_off   = ((lane >> 3) & 1) * 8;

    for (int kt = kt_lo; kt < kt_hi; kt++) {
        const int buf = (kt - kt_lo) & 1;
        __syncthreads();

        if (kt + 1 < kt_hi) {
            load_kv(buf ^ 1, kt + 1);
            CP_WAIT(1);
        } else {
            CP_WAIT(0);
        }
        __syncthreads();

        const unsigned kH = sb + FL_KB + buf * 34816;
        const unsigned kL = kH + 17408;
        const unsigned vH = sb + FL_VB + buf * 36864;
        const unsigned vL = vH + 18432;

        // ---- S = Q K^T (128x64 tile, this warp: 16 rows) ----
        float s[8][4];
#pragma unroll
        for (int n = 0; n < 8; n++)
#pragma unroll
            for (int q = 0; q < 4; q++) s[n][q] = 0.f;

#pragma unroll
        for (int t = 0; t < 8; t++) {
            const int kb = t * 16;
            unsigned aoff = (unsigned)((wm * 16 + a_row_off) * FL_QROWB + (kb + a_kb_off) * 2);
            unsigned ah[4], al[4];
            ldsm_x4(sb + FL_QH + aoff, ah[0], ah[1], ah[2], ah[3]);
            ldsm_x4(sb + FL_QL + aoff, al[0], al[1], al[2], al[3]);
#pragma unroll
            for (int g = 0; g < 4; g++) {
                unsigned boff = (unsigned)((g * 16 + b_n_off) * FL_KROWB + (kb + b_k_off) * 2);
                unsigned bh[4], bl[4];
                ldsm_x4(kH + boff, bh[0], bh[1], bh[2], bh[3]);
                ldsm_x4(kL + boff, bl[0], bl[1], bl[2], bl[3]);
                mma_bf16(s[2*g],   ah, bh);     mma_bf16(s[2*g],   ah, bl);
                mma_bf16(s[2*g],   al, bh);
                mma_bf16(s[2*g+1], ah, bh + 2); mma_bf16(s[2*g+1], ah, bl + 2);
                mma_bf16(s[2*g+1], al, bh + 2);
            }
        }

        // ---- causal mask (only near diagonal) ----
        const int qr0 = qt * 128 + wm * 16 + (lane >> 2);
        const int qr1 = qr0 + 8;
        if (kt * 64 + 63 > qt * 128 + wm * 16) {
#pragma unroll
            for (int n = 0; n < 8; n++) {
                int c0 = kt * 64 + n * 8 + (lane & 3) * 2;
                if (c0     > qr0) s[n][0] = -1e30f;
                if (c0 + 1 > qr0) s[n][1] = -1e30f;
                if (c0     > qr1) s[n][2] = -1e30f;
                if (c0 + 1 > qr1) s[n][3] = -1e30f;
            }
        }

        // ---- online softmax (rows warp-local, 4 lanes/row) ----
        float mx0 = -1e30f, mx1 = -1e30f;
#pragma unroll
        for (int n = 0; n < 8; n++) {
            mx0 = fmaxf(mx0, fmaxf(s[n][0], s[n][1]));
            mx1 = fmaxf(mx1, fmaxf(s[n][2], s[n][3]));
        }
        mx0 = fmaxf(mx0, __shfl_xor_sync(0xffffffffu, mx0, 1));
        mx0 = fmaxf(mx0, __shfl_xor_sync(0xffffffffu, mx0, 2));
        mx1 = fmaxf(mx1, __shfl_xor_sync(0xffffffffu, mx1, 1));
        mx1 = fmaxf(mx1, __shfl_xor_sync(0xffffffffu, mx1, 2));

        const float mn0 = fmaxf(m0, mx0);
        const float mn1 = fmaxf(m1, mx1);
        const float fac0 = __expf(m0 - mn0);
        const float fac1 = __expf(m1 - mn1);

        unsigned pAh[4][4], pAl[4][4];
        float ls0 = 0.f, ls1 = 0.f;
#pragma unroll
        for (int t = 0; t < 4; t++) {
            float p00 = __expf(s[2*t][0] - mn0),   p01 = __expf(s[2*t][1] - mn0);
            float p02 = __expf(s[2*t][2] - mn1),   p03 = __expf(s[2*t][3] - mn1);
            float p10 = __expf(s[2*t+1][0] - mn0), p11 = __expf(s[2*t+1][1] - mn0);
            float p12 = __expf(s[2*t+1][2] - mn1), p13 = __expf(s[2*t+1][3] - mn1);
            ls0 += (p00 + p01) + (p10 + p11);
            ls1 += (p02 + p03) + (p12 + p13);
            pAh[t][0] = cvt2_bf16(p00, p01);
            pAh[t][1] = cvt2_bf16(p02, p03);
            pAh[t][2] = cvt2_bf16(p10, p11);
            pAh[t][3] = cvt2_bf16(p12, p13);
            pAl[t][0] = cvt2_bf16(p00 - bf16_round(p00), p01 - bf16_round(p01));
            pAl[t][1] = cvt2_bf16(p02 - bf16_round(p02), p03 - bf16_round(p03));
            pAl[t][2] = cvt2_bf16(p10 - bf16_round(p10), p11 - bf16_round(p11));
            pAl[t][3] = cvt2_bf16(p12 - bf16_round(p12), p13 - bf16_round(p13));
        }
        l0 = l0 * fac0 + ls0;
        l1 = l1 * fac1 + ls1;
        m0 = mn0; m1 = mn1;
#pragma unroll
        for (int n = 0; n < 16; n++) {
            o[n][0] *= fac0; o[n][1] *= fac0;
            o[n][2] *= fac1; o[n][3] *= fac1;
        }

        // ---- O += P @ V (B = W_V[h][k], n = h) ----
#pragma unroll
        for (int t = 0; t < 4; t++) {
#pragma unroll
            for (int g = 0; g < 8; g++) {
                unsigned boff = (unsigned)((g * 16 + b_n_off) * FL_VROWB + (t * 16 + b_k_off) * 2);
                unsigned bh[4], bl[4];
                ldsm_x4(vH + boff, bh[0], bh[1], bh[2], bh[3]);
                ldsm_x4(vL + boff, bl[0], bl[1], bl[2], bl[3]);
                mma_bf16(o[2*g],   pAh[t], bh);     mma_bf16(o[2*g],   pAh[t], bl);
                mma_bf16(o[2*g],   pAl[t], bh);
                mma_bf16(o[2*g+1], pAh[t], bh + 2); mma_bf16(o[2*g+1], pAh[t], bl + 2);
                mma_bf16(o[2*g+1], pAl[t], bh + 2);
            }
        }
    }

    // ---- epilogue ----
    l0 += __shfl_xor_sync(0xffffffffu, l0, 1);
    l0 += __shfl_xor_sync(0xffffffffu, l0, 2);
    l1 += __shfl_xor_sync(0xffffffffu, l1, 1);
    l1 += __shfl_xor_sync(0xffffffffu, l1, 2);

    const int r0 = wm * 16 + (lane >> 2);
    float* __restrict__ Og = g_O[sp] + (qrow0) * HEAD;
#pragma unroll
    for (int n = 0; n < 16; n++) {
        const int col = n * 8 + (lane & 3) * 2;
        *(float2*)&Og[(long)r0 * HEAD + col]       = make_float2(o[n][0], o[n][1]);
        *(float2*)&Og[(long)(r0 + 8) * HEAD + col] = make_float2(o[n][2], o[n][3]);
    }
    if ((lane & 3) == 0) {
        const long rowg = (long)b * SEQ + qt * 128 + r0;
        g_m[sp][rowg] = m0;     g_l[sp][rowg] = l0;
        g_m[sp][rowg + 8] = m1; g_l[sp][rowg + 8] = l1;
    }
}

// ---------------------------------------------------------------------------
// Combine 4 splits: out = sum_s w_s O_s / sum_s w_s l_s
// ---------------------------------------------------------------------------
__global__ void combine_kernel(float* __restrict__ out)
{
    int id = blockIdx.x * 256 + threadIdx.x;
    int row = id >> 7;
    float mv[NSPLIT], lv[NSPLIT];
    float M = -1e30f;
#pragma unroll
    for (int s = 0; s < NSPLIT; s++) {
        mv[s] = g_m[s][row];
        lv[s] = g_l[s][row];
        M = fmaxf(M, mv[s]);
    }
    float num = 0.f, den = 0.f;
#pragma unroll
    for (int s = 0; s < NSPLIT; s++) {
        float w = __expf(mv[s] - M);
        num += w * g_O[s][id];
        den += w * lv[s];
    }
    out[id] = num / den;
}

// ---------------------------------------------------------------------------
extern "C" void kernel_launch(void* const* d_in, const int* in_sizes, int n_in,
                              void* d_out, int out_size)
{
    const float* X  = (const float*)d_in[0];
    const float* WQ = (const float*)d_in[1];
    const float* WK = (const float*)d_in[2];
    const float* WV = (const float*)d_in[3];
    float* out = (float*)d_out;

    cudaFuncSetAttribute(proj_mma_kernel,
                         cudaFuncAttributeMaxDynamicSharedMemorySize, PJ_SMEM);
    cudaFuncSetAttribute(flash_kernel,
                         cudaFuncAttributeMaxDynamicSharedMemorySize, FL_SMEM);

    convert_x_kernel<<<(BATCH*SEQ*EMB)/1024, 256>>>(X);                  // 0
    convert_wv_kernel<<<(384*EMB)/1024, 256>>>(WQ, WK, WV);              // 1
    proj_mma_kernel<<<dim3(64, 2), 256, PJ_SMEM>>>();                    // 2
    flash_kernel<<<BATCH * 16 * NSPLIT, 256, FL_SMEM>>>();               // 3 (ncu)
    combine_kernel<<<(BATCH * SEQ * HEAD) / 256, 256>>>(out);            // 4
}

// round 7
// speedup vs baseline: 4.9053x; 1.0783x over previous
#include <cuda_runtime.h>
#include <cuda_bf16.h>
#include <math.h>
#include <cstdint>

#define BATCH 4
#define SEQ   2048
#define EMB   2048
#define HEAD  128
#define NSPLIT 4

// ------------------------- device scratch -------------------------
__device__ __nv_bfloat16 g_Xhi[BATCH*SEQ*EMB];
__device__ __nv_bfloat16 g_Xlo[BATCH*SEQ*EMB];
__device__ __nv_bfloat16 g_Bhi[256*EMB];     // rows 0-127: WQ, 128-255: WK
__device__ __nv_bfloat16 g_Blo[256*EMB];
__device__ __nv_bfloat16 g_Vhi[HEAD*EMB];    // W_V as-is: [h][k]
__device__ __nv_bfloat16 g_Vlo[HEAD*EMB];
__device__ __nv_bfloat16 g_Qhi[BATCH*SEQ*HEAD];  // pre-scaled by 1/sqrt(128)
__device__ __nv_bfloat16 g_Qlo[BATCH*SEQ*HEAD];
__device__ __nv_bfloat16 g_Khi[BATCH*SEQ*HEAD];
__device__ __nv_bfloat16 g_Klo[BATCH*SEQ*HEAD];
__device__ float g_O[NSPLIT][BATCH*SEQ*HEAD];    // unnormalized partial O
__device__ float g_m[NSPLIT][BATCH*SEQ];
__device__ float g_l[NSPLIT][BATCH*SEQ];

// ------------------------- helpers -------------------------
__device__ __forceinline__ void cp16s(unsigned sd, const void* gsrc) {
    asm volatile("cp.async.cg.shared.global [%0], [%1], 16;\n" :: "r"(sd), "l"(gsrc));
}
#define CP_COMMIT() asm volatile("cp.async.commit_group;\n" ::: "memory")
#define CP_WAIT(N)  asm volatile("cp.async.wait_group %0;\n" :: "n"(N) : "memory")

__device__ __forceinline__ unsigned smem_u32(const void* p) {
    return (unsigned)__cvta_generic_to_shared((void*)p);
}
__device__ __forceinline__ void ldsm_x4(unsigned addr, unsigned& r0, unsigned& r1,
                                        unsigned& r2, unsigned& r3) {
    asm volatile("ldmatrix.sync.aligned.m8n8.x4.shared.b16 {%0,%1,%2,%3}, [%4];"
                 : "=r"(r0), "=r"(r1), "=r"(r2), "=r"(r3) : "r"(addr));
}
__device__ __forceinline__ void mma_bf16(float* c, const unsigned* a, const unsigned* b) {
    asm volatile(
        "mma.sync.aligned.m16n8k16.row.col.f32.bf16.bf16.f32 "
        "{%0,%1,%2,%3}, {%4,%5,%6,%7}, {%8,%9}, {%0,%1,%2,%3};"
        : "+f"(c[0]), "+f"(c[1]), "+f"(c[2]), "+f"(c[3])
        : "r"(a[0]), "r"(a[1]), "r"(a[2]), "r"(a[3]), "r"(b[0]), "r"(b[1]));
}
__device__ __forceinline__ unsigned cvt2_bf16(float lo_val, float hi_val) {
    unsigned r;
    asm("cvt.rn.bf16x2.f32 %0, %1, %2;" : "=r"(r) : "f"(hi_val), "f"(lo_val));
    return r;
}
__device__ __forceinline__ float bf16_round(float x) {
    return __bfloat162float(__float2bfloat16(x));
}

// ---------------------------------------------------------------------------
// convert X -> (hi, lo) bf16 split
// ---------------------------------------------------------------------------
__global__ __launch_bounds__(256) void convert_x_kernel(const float* __restrict__ X)
{
    long i = ((long)blockIdx.x * 256 + threadIdx.x) * 4;
    float4 v = *(const float4*)(X + i);
    float vv[4] = {v.x, v.y, v.z, v.w};
    __nv_bfloat16 hi[4], lo[4];
#pragma unroll
    for (int q = 0; q < 4; q++) {
        hi[q] = __float2bfloat16(vv[q]);
        lo[q] = __float2bfloat16(vv[q] - __bfloat162float(hi[q]));
    }
    *(ushort4*)&g_Xhi[i] = *(ushort4*)hi;
    *(ushort4*)&g_Xlo[i] = *(ushort4*)lo;
}

// ---------------------------------------------------------------------------
// convert WQ/WK/WV
// ---------------------------------------------------------------------------
__global__ __launch_bounds__(256) void convert_wv_kernel(
    const float* __restrict__ WQ, const float* __restrict__ WK,
    const float* __restrict__ WV)
{
    long i = ((long)blockIdx.x * 256 + threadIdx.x) * 4;
    const float* src;
    __nv_bfloat16 *dhi, *dlo;
    long didx;
    if (i < 256L * EMB) {
        int r = (int)(i >> 11);
        long c = i & 2047;
        src = (r < 128) ? (WQ + (long)r * EMB + c) : (WK + (long)(r - 128) * EMB + c);
        dhi = g_Bhi; dlo = g_Blo; didx = i;
    } else {
        long j = i - 256L * EMB;
        src = WV + j;
        dhi = g_Vhi; dlo = g_Vlo; didx = j;
    }
    float4 v = *(const float4*)src;
    float vv[4] = {v.x, v.y, v.z, v.w};
    __nv_bfloat16 hi[4], lo[4];
#pragma unroll
    for (int q = 0; q < 4; q++) {
        hi[q] = __float2bfloat16(vv[q]);
        lo[q] = __float2bfloat16(vv[q] - __bfloat162float(hi[q]));
    }
    *(ushort4*)&dhi[didx] = *(ushort4*)hi;
    *(ushort4*)&dlo[didx] = *(ushort4*)lo;
}

// ---------------------------------------------------------------------------
// mma.sync projection GEMM: Q/K(8192 x 128 each) = X @ B^T (bf16x3 split)
// CTA 128x128 (grid 64 x 2), BK=64, double-buffered cp.async, 8 warps (4m x 2n)
// Term-major MMA ordering for accumulator-chain spacing.
// ---------------------------------------------------------------------------
#define PJ_ROWB  144                  // 64 bf16 = 128 B data + 16 B pad
#define PJ_ARR   (128*PJ_ROWB)        // 18432 B per tile array
#define PJ_BUF   (4*PJ_ARR)           // A_hi A_lo B_hi B_lo = 73728 B
#define PJ_SMEM  (2*PJ_BUF)           // 147456 B

__global__ __launch_bounds__(256) void proj_mma_kernel()
{
    extern __shared__ unsigned char dsm8[];
    const unsigned sb = smem_u32(dsm8);

    const int tid = threadIdx.x;
    const int wid = tid >> 5;
    const int lane = tid & 31;
    const int wm = wid & 3;
    const int wn = wid >> 2;

    const int m0 = blockIdx.x * 128;
    const int nt = blockIdx.y;     // 0 -> Q, 1 -> K

    float acc[2][8][4];
#pragma unroll
    for (int m = 0; m < 2; m++)
#pragma unroll
        for (int n = 0; n < 8; n++)
#pragma unroll
            for (int q = 0; q < 4; q++) acc[m][n][q] = 0.f;

    auto load_tile = [&](int buf, int kt) {
        const unsigned base = sb + buf * PJ_BUF;
        const long kof = (long)kt * 64;
        for (int c = tid; c < 1024; c += 256) {
            int r = c >> 3, ch = c & 7;
            unsigned so = (unsigned)(r * PJ_ROWB + ch * 16);
            const long gix = (long)(m0 + r) * EMB + kof + ch * 8;
            cp16s(base + so,          g_Xhi + gix);
            cp16s(base + PJ_ARR + so, g_Xlo + gix);
        }
        for (int c = tid; c < 1024; c += 256) {
            int r = c >> 3, ch = c & 7;
            unsigned so = (unsigned)(r * PJ_ROWB + ch * 16);
            const long gix = (long)(nt * 128 + r) * EMB + kof + ch * 8;
            cp16s(base + 2*PJ_ARR + so, g_Bhi + gix);
            cp16s(base + 3*PJ_ARR + so, g_Blo + gix);
        }
        CP_COMMIT();
    };

    load_tile(0, 0);

    const int a_row_off = (lane & 7) + ((lane >> 3) & 1) * 8;
    const int a_kb_off  = (lane >> 4) * 8;
    const int b_n_off   = (lane & 7) + ((lane >> 3) >> 1) * 8;
    const int b_k_off   = ((lane >> 3) & 1) * 8;

    for (int kt = 0; kt < 32; kt++) {
        const int buf = kt & 1;
        __syncthreads();

        if (kt + 1 < 32) {
            load_tile(buf ^ 1, kt + 1);
            CP_WAIT(1);
        } else {
            CP_WAIT(0);
        }
        __syncthreads();

        const unsigned aH = sb + buf * PJ_BUF;
        const unsigned aL = aH + PJ_ARR;
        const unsigned bH = aH + 2*PJ_ARR;
        const unsigned bL = aH + 3*PJ_ARR;

#pragma unroll
        for (int kf = 0; kf < 4; kf++) {
            const int kb = kf * 16;
            unsigned ah[2][4], al[2][4];
#pragma unroll
            for (int m = 0; m < 2; m++) {
                unsigned row = (unsigned)(wm * 32 + m * 16 + a_row_off);
                unsigned off = row * PJ_ROWB + (unsigned)(kb + a_kb_off) * 2;
                ldsm_x4(aH + off, ah[m][0], ah[m][1], ah[m][2], ah[m][3]);
                ldsm_x4(aL + off, al[m][0], al[m][1], al[m][2], al[m][3]);
            }
            unsigned bh[8][2], bl[8][2];
#pragma unroll
            for (int g = 0; g < 4; g++) {
                unsigned nrow = (unsigned)(wn * 64 + g * 16 + b_n_off);
                unsigned off = nrow * PJ_ROWB + (unsigned)(kb + b_k_off) * 2;
                ldsm_x4(bH + off, bh[g*2][0], bh[g*2][1], bh[g*2+1][0], bh[g*2+1][1]);
                ldsm_x4(bL + off, bl[g*2][0], bl[g*2][1], bl[g*2+1][0], bl[g*2+1][1]);
            }
            // term-major: 16 independent MMAs per term
#pragma unroll
            for (int m = 0; m < 2; m++)
#pragma unroll
                for (int n = 0; n < 8; n++) mma_bf16(acc[m][n], ah[m], bh[n]);
#pragma unroll
            for (int m = 0; m < 2; m++)
#pragma unroll
                for (int n = 0; n < 8; n++) mma_bf16(acc[m][n], ah[m], bl[n]);
#pragma unroll
            for (int m = 0; m < 2; m++)
#pragma unroll
                for (int n = 0; n < 8; n++) mma_bf16(acc[m][n], al[m], bh[n]);
        }
    }

    // ---- epilogue: write bf16 hi/lo (Q pre-scaled) ----
    __nv_bfloat16* __restrict__ dhi = nt ? g_Khi : g_Qhi;
    __nv_bfloat16* __restrict__ dlo = nt ? g_Klo : g_Qlo;
    const float scl = nt ? 1.0f : 0.08838834764831845f;
#pragma unroll
    for (int m = 0; m < 2; m++) {
        const int row = m0 + wm * 32 + m * 16 + (lane >> 2);
#pragma unroll
        for (int n = 0; n < 8; n++) {
            const int col = wn * 64 + n * 8 + (lane & 3) * 2;
            float v0 = acc[m][n][0] * scl, v1 = acc[m][n][1] * scl;
            float v2 = acc[m][n][2] * scl, v3 = acc[m][n][3] * scl;
            *(unsigned*)&dhi[(long)row * HEAD + col] = cvt2_bf16(v0, v1);
            *(unsigned*)&dlo[(long)row * HEAD + col] =
                cvt2_bf16(v0 - bf16_round(v0), v1 - bf16_round(v1));
            *(unsigned*)&dhi[(long)(row + 8) * HEAD + col] = cvt2_bf16(v2, v3);
            *(unsigned*)&dlo[(long)(row + 8) * HEAD + col] =
                cvt2_bf16(v2 - bf16_round(v2), v3 - bf16_round(v3));
        }
    }
}

// ---------------------------------------------------------------------------
// Tensor-core causal flash attention, bf16x3 split, split-K(4).
// CTA: 128 q-rows x 64 k-tile, 8 warps (16 rows each). Double-buffered K/V.
// Term-major MMA ordering.
// ---------------------------------------------------------------------------
#define FL_QROWB 272
#define FL_KROWB 272
#define FL_VROWB 144
#define FL_QH 0
#define FL_QL 34816
#define FL_KB 69632
#define FL_VB 139264
#define FL_SMEM 212992

__global__ __launch_bounds__(256) void flash_kernel()
{
    extern __shared__ unsigned char dsm8[];
    const unsigned sb = smem_u32(dsm8);

    const int tid = threadIdx.x;
    const int wm  = tid >> 5;
    const int lane = tid & 31;

    const int bid = blockIdx.x;
    const int qt = 15 - (bid >> 4);
    const int b  = (bid >> 2) & 3;
    const int sp = bid & 3;

    const int nkt   = 2 * (qt + 1);
    const int chunk = (nkt + NSPLIT - 1) / NSPLIT;
    const int kt_lo = sp * chunk;
    const int kt_hi = min(nkt, kt_lo + chunk);

    const long qrow0 = (long)b * SEQ + qt * 128;

    for (int c = tid; c < 2048; c += 256) {
        int r = c >> 4, ch = c & 15;
        unsigned so = (unsigned)(r * FL_QROWB + ch * 16);
        const long gix = (qrow0 + r) * HEAD + ch * 8;
        cp16s(sb + FL_QH + so, g_Qhi + gix);
        cp16s(sb + FL_QL + so, g_Qlo + gix);
    }

    auto load_kv = [&](int buf, int kt) {
        const unsigned kh = sb + FL_KB + buf * 34816;
        const unsigned vh = sb + FL_VB + buf * 36864;
        for (int c = tid; c < 1024; c += 256) {
            int r = c >> 4, ch = c & 15;
            unsigned so = (unsigned)(r * FL_KROWB + ch * 16);
            const long gix = ((long)b * SEQ + kt * 64 + r) * HEAD + ch * 8;
            cp16s(kh + so,         g_Khi + gix);
            cp16s(kh + 17408 + so, g_Klo + gix);
        }
        for (int c = tid; c < 1024; c += 256) {
            int r = c >> 3, ch = c & 7;
            unsigned so = (unsigned)(r * FL_VROWB + ch * 16);
            const long gix = (long)r * EMB + kt * 64 + ch * 8;
            cp16s(vh + so,         g_Vhi + gix);
            cp16s(vh + 18432 + so, g_Vlo + gix);
        }
        CP_COMMIT();
    };

    if (kt_lo < kt_hi) load_kv(0, kt_lo);
    else CP_COMMIT();

    float o[16][4];
#pragma unroll
    for (int n = 0; n < 16; n++)
#pragma unroll
        for (int q = 0; q < 4; q++) o[n][q] = 0.f;
    float m0 = -1e30f, m1 = -1e30f;
    float l0 = 0.f, l1 = 0.f;

    const int a_row_off = (lane & 7) + ((lane >> 3) & 1) * 8;
    const int a_kb_off  = (lane >> 4) * 8;
    const int b_n_off   = (lane & 7) + ((lane >> 3) >> 1) * 8;
    const int b_k_off   = ((lane >> 3) & 1) * 8;

    for (int kt = kt_lo; kt < kt_hi; kt++) {
        const int buf = (kt - kt_lo) & 1;
        __syncthreads();

        if (kt + 1 < kt_hi) {
            load_kv(buf ^ 1, kt + 1);
            CP_WAIT(1);
        } else {
            CP_WAIT(0);
        }
        __syncthreads();

        const unsigned kH = sb + FL_KB + buf * 34816;
        const unsigned kL = kH + 17408;
        const unsigned vH = sb + FL_VB + buf * 36864;
        const unsigned vL = vH + 18432;

        // ---- S = Q K^T ----
        float s[8][4];
#pragma unroll
        for (int n = 0; n < 8; n++)
#pragma unroll
            for (int q = 0; q < 4; q++) s[n][q] = 0.f;

#pragma unroll
        for (int t = 0; t < 8; t++) {
            const int kb = t * 16;
            unsigned aoff = (unsigned)((wm * 16 + a_row_off) * FL_QROWB + (kb + a_kb_off) * 2);
            unsigned ah[4], al[4];
            ldsm_x4(sb + FL_QH + aoff, ah[0], ah[1], ah[2], ah[3]);
            ldsm_x4(sb + FL_QL + aoff, al[0], al[1], al[2], al[3]);
            unsigned bh[4][4], bl[4][4];
#pragma unroll
            for (int g = 0; g < 4; g++) {
                unsigned boff = (unsigned)((g * 16 + b_n_off) * FL_KROWB + (kb + b_k_off) * 2);
                ldsm_x4(kH + boff, bh[g][0], bh[g][1], bh[g][2], bh[g][3]);
                ldsm_x4(kL + boff, bl[g][0], bl[g][1], bl[g][2], bl[g][3]);
            }
            // term-major: 8 independent MMAs per term
#pragma unroll
            for (int g = 0; g < 4; g++) {
                mma_bf16(s[2*g],   ah, bh[g]);
                mma_bf16(s[2*g+1], ah, bh[g] + 2);
            }
#pragma unroll
            for (int g = 0; g < 4; g++) {
                mma_bf16(s[2*g],   ah, bl[g]);
                mma_bf16(s[2*g+1], ah, bl[g] + 2);
            }
#pragma unroll
            for (int g = 0; g < 4; g++) {
                mma_bf16(s[2*g],   al, bh[g]);
                mma_bf16(s[2*g+1], al, bh[g] + 2);
            }
        }

        // ---- causal mask ----
        const int qr0 = qt * 128 + wm * 16 + (lane >> 2);
        const int qr1 = qr0 + 8;
        if (kt * 64 + 63 > qt * 128 + wm * 16) {
#pragma unroll
            for (int n = 0; n < 8; n++) {
                int c0 = kt * 64 + n * 8 + (lane & 3) * 2;
                if (c0     > qr0) s[n][0] = -1e30f;
                if (c0 + 1 > qr0) s[n][1] = -1e30f;
                if (c0     > qr1) s[n][2] = -1e30f;
                if (c0 + 1 > qr1) s[n][3] = -1e30f;
            }
        }

        // ---- online softmax ----
        float mx0 = -1e30f, mx1 = -1e30f;
#pragma unroll
        for (int n = 0; n < 8; n++) {
            mx0 = fmaxf(mx0, fmaxf(s[n][0], s[n][1]));
            mx1 = fmaxf(mx1, fmaxf(s[n][2], s[n][3]));
        }
        mx0 = fmaxf(mx0, __shfl_xor_sync(0xffffffffu, mx0, 1));
        mx0 = fmaxf(mx0, __shfl_xor_sync(0xffffffffu, mx0, 2));
        mx1 = fmaxf(mx1, __shfl_xor_sync(0xffffffffu, mx1, 1));
        mx1 = fmaxf(mx1, __shfl_xor_sync(0xffffffffu, mx1, 2));

        const float mn0 = fmaxf(m0, mx0);
        const float mn1 = fmaxf(m1, mx1);
        const float fac0 = __expf(m0 - mn0);
        const float fac1 = __expf(m1 - mn1);

        unsigned pAh[4][4], pAl[4][4];
        float ls0 = 0.f, ls1 = 0.f;
#pragma unroll
        for (int t = 0; t < 4; t++) {
            float p00 = __expf(s[2*t][0] - mn0),   p01 = __expf(s[2*t][1] - mn0);
            float p02 = __expf(s[2*t][2] - mn1),   p03 = __expf(s[2*t][3] - mn1);
            float p10 = __expf(s[2*t+1][0] - mn0), p11 = __expf(s[2*t+1][1] - mn0);
            float p12 = __expf(s[2*t+1][2] - mn1), p13 = __expf(s[2*t+1][3] - mn1);
            ls0 += (p00 + p01) + (p10 + p11);
            ls1 += (p02 + p03) + (p12 + p13);
            pAh[t][0] = cvt2_bf16(p00, p01);
            pAh[t][1] = cvt2_bf16(p02, p03);
            pAh[t][2] = cvt2_bf16(p10, p11);
            pAh[t][3] = cvt2_bf16(p12, p13);
            pAl[t][0] = cvt2_bf16(p00 - bf16_round(p00), p01 - bf16_round(p01));
            pAl[t][1] = cvt2_bf16(p02 - bf16_round(p02), p03 - bf16_round(p03));
            pAl[t][2] = cvt2_bf16(p10 - bf16_round(p10), p11 - bf16_round(p11));
            pAl[t][3] = cvt2_bf16(p12 - bf16_round(p12), p13 - bf16_round(p13));
        }
        l0 = l0 * fac0 + ls0;
        l1 = l1 * fac1 + ls1;
        m0 = mn0; m1 = mn1;
#pragma unroll
        for (int n = 0; n < 16; n++) {
            o[n][0] *= fac0; o[n][1] *= fac0;
            o[n][2] *= fac1; o[n][3] *= fac1;
        }

        // ---- O += P @ V (term-major, g split in halves of 4) ----
#pragma unroll
        for (int t = 0; t < 4; t++) {
#pragma unroll
            for (int h = 0; h < 2; h++) {
                unsigned vhr[4][4], vlr[4][4];
#pragma unroll
                for (int g4 = 0; g4 < 4; g4++) {
                    const int g = h * 4 + g4;
                    unsigned boff = (unsigned)((g * 16 + b_n_off) * FL_VROWB + (t * 16 + b_k_off) * 2);
                    ldsm_x4(vH + boff, vhr[g4][0], vhr[g4][1], vhr[g4][2], vhr[g4][3]);
                    ldsm_x4(vL + boff, vlr[g4][0], vlr[g4][1], vlr[g4][2], vlr[g4][3]);
                }
#pragma unroll
                for (int g4 = 0; g4 < 4; g4++) {
                    const int g = h * 4 + g4;
                    mma_bf16(o[2*g],   pAh[t], vhr[g4]);
                    mma_bf16(o[2*g+1], pAh[t], vhr[g4] + 2);
                }
#pragma unroll
                for (int g4 = 0; g4 < 4; g4++) {
                    const int g = h * 4 + g4;
                    mma_bf16(o[2*g],   pAh[t], vlr[g4]);
                    mma_bf16(o[2*g+1], pAh[t], vlr[g4] + 2);
                }
#pragma unroll
                for (int g4 = 0; g4 < 4; g4++) {
                    const int g = h * 4 + g4;
                    mma_bf16(o[2*g],   pAl[t], vhr[g4]);
                    mma_bf16(o[2*g+1], pAl[t], vhr[g4] + 2);
                }
            }
        }
    }

    // ---- epilogue ----
    l0 += __shfl_xor_sync(0xffffffffu, l0, 1);
    l0 += __shfl_xor_sync(0xffffffffu, l0, 2);
    l1 += __shfl_xor_sync(0xffffffffu, l1, 1);
    l1 += __shfl_xor_sync(0xffffffffu, l1, 2);

    const int r0 = wm * 16 + (lane >> 2);
    float* __restrict__ Og = g_O[sp] + (qrow0) * HEAD;
#pragma unroll
    for (int n = 0; n < 16; n++) {
        const int col = n * 8 + (lane & 3) * 2;
        *(float2*)&Og[(long)r0 * HEAD + col]       = make_float2(o[n][0], o[n][1]);
        *(float2*)&Og[(long)(r0 + 8) * HEAD + col] = make_float2(o[n][2], o[n][3]);
    }
    if ((lane & 3) == 0) {
        const long rowg = (long)b * SEQ + qt * 128 + r0;
        g_m[sp][rowg] = m0;     g_l[sp][rowg] = l0;
        g_m[sp][rowg + 8] = m1; g_l[sp][rowg + 8] = l1;
    }
}

// ---------------------------------------------------------------------------
__global__ void combine_kernel(float* __restrict__ out)
{
    int id = blockIdx.x * 256 + threadIdx.x;
    int row = id >> 7;
    float mv[NSPLIT], lv[NSPLIT];
    float M = -1e30f;
#pragma unroll
    for (int s = 0; s < NSPLIT; s++) {
        mv[s] = g_m[s][row];
        lv[s] = g_l[s][row];
        M = fmaxf(M, mv[s]);
    }
    float num = 0.f, den = 0.f;
#pragma unroll
    for (int s = 0; s < NSPLIT; s++) {
        float w = __expf(mv[s] - M);
        num += w * g_O[s][id];
        den += w * lv[s];
    }
    out[id] = num / den;
}

// ---------------------------------------------------------------------------
extern "C" void kernel_launch(void* const* d_in, const int* in_sizes, int n_in,
                              void* d_out, int out_size)
{
    const float* X  = (const float*)d_in[0];
    const float* WQ = (const float*)d_in[1];
    const float* WK = (const float*)d_in[2];
    const float* WV = (const float*)d_in[3];
    float* out = (float*)d_out;

    cudaFuncSetAttribute(proj_mma_kernel,
                         cudaFuncAttributeMaxDynamicSharedMemorySize, PJ_SMEM);
    cudaFuncSetAttribute(flash_kernel,
                         cudaFuncAttributeMaxDynamicSharedMemorySize, FL_SMEM);

    convert_x_kernel<<<(BATCH*SEQ*EMB)/1024, 256>>>(X);                  // 0
    convert_wv_kernel<<<(384*EMB)/1024, 256>>>(WQ, WK, WV);              // 1
    proj_mma_kernel<<<dim3(64, 2), 256, PJ_SMEM>>>();                    // 2
    flash_kernel<<<BATCH * 16 * NSPLIT, 256, FL_SMEM>>>();               // 3 (ncu)
    combine_kernel<<<(BATCH * SEQ * HEAD) / 256, 256>>>(out);            // 4
}